// round 9
// baseline (speedup 1.0000x reference)
#include <cuda_runtime.h>
#include <cuda_fp16.h>
#include <cstdint>

#define NDRUG 100000
#define NPROT 100000
#define NN    100000
#define NEMAX 800000
#define DIM   128
#define KC    32        // k-chunk
#define SAK   36        // smem chunk row stride (floats)
#define GBLK  782       // ceil(100000/128)

// ---------------- scratch ----------------
// fp16 feature buffers (ping-pong): A = inputs / layer2 out, B = layer1 out
__device__ __half g_hA_d[(size_t)NN * DIM];
__device__ __half g_hA_p[(size_t)NN * DIM];
__device__ __half g_hB_d[(size_t)NN * DIM];
__device__ __half g_hB_p[(size_t)NN * DIM];
__device__ float g_agg1[(size_t)NDRUG * DIM];
__device__ float g_agg2[(size_t)NDRUG * DIM];
__device__ float g_aggp[(size_t)NPROT * DIM];
// [0]=ddi_out [1]=ddi_in [2]=pdi_out [3]=pdi_in [4]=ppi_out [5]=ppi_in
__device__ float g_rs[(size_t)6 * NN];
__device__ float g_Wt[(size_t)9 * DIM * DIM];
__device__ int g_indptr[3 * (NN + 1)];
__device__ int g_cursor[3 * NN];
__device__ int g_eidx[3 * NEMAX];
__device__ int g_bsum[3 * 128];

// ---------------- helpers ----------------
__device__ __forceinline__ uint32_t sptr(const void* p) {
    return (uint32_t)__cvta_generic_to_shared(p);
}
__device__ __forceinline__ void cp_async16(uint32_t dst, const void* src, int sz) {
    asm volatile("cp.async.cg.shared.global [%0], [%1], 16, %2;" :: "r"(dst), "l"(src), "r"(sz));
}
__device__ __forceinline__ void mma_tf32(float c[4], const uint32_t a[4], const uint32_t b[2]) {
    asm volatile(
        "mma.sync.aligned.m16n8k8.row.col.f32.tf32.tf32.f32 "
        "{%0,%1,%2,%3}, {%4,%5,%6,%7}, {%8,%9}, {%0,%1,%2,%3};"
        : "+f"(c[0]), "+f"(c[1]), "+f"(c[2]), "+f"(c[3])
        : "r"(a[0]), "r"(a[1]), "r"(a[2]), "r"(a[3]), "r"(b[0]), "r"(b[1]));
}

// ---------------- preprocessing kernels ----------------
// launch #0: zero the degree-count arrays
__global__ void zero_rs(float* __restrict__ rs) {
    int i = blockIdx.x * blockDim.x + threadIdx.x;
    if (i < 6 * NN) rs[i] = 0.0f;
}
// launch #1: batched degree count (grid.y = relation)
__global__ void count2b(const int* __restrict__ s0, const int* __restrict__ d0, int n0,
                        const int* __restrict__ s1, const int* __restrict__ d1, int n1,
                        const int* __restrict__ s2, const int* __restrict__ d2, int n2,
                        float* __restrict__ rs) {
    const int rel = blockIdx.y;
    const int* src = rel == 0 ? s0 : (rel == 1 ? s1 : s2);
    const int* dst = rel == 0 ? d0 : (rel == 1 ? d1 : d2);
    int n = rel == 0 ? n0 : (rel == 1 ? n1 : n2);
    float* cs = rs + (size_t)(2 * rel) * NN;
    float* cd = rs + (size_t)(2 * rel + 1) * NN;
    int i = blockIdx.x * blockDim.x + threadIdx.x;
    if (i < n) {
        atomicAdd(&cs[src[i]], 1.0f);
        atomicAdd(&cd[dst[i]], 1.0f);
    }
}
// launch #2: per-1024-block scan of in-degree counts
__global__ void scan1(const float* __restrict__ rs, int* __restrict__ indptr,
                      int* __restrict__ bsum) {
    __shared__ int sm2[1024];
    const int rel = blockIdx.y;
    const float* cnt = rs + (size_t)(2 * rel + 1) * NN;
    int* excl = indptr + rel * (NN + 1);
    int tid = threadIdx.x;
    int i = blockIdx.x * 1024 + tid;
    int v = (i < NN) ? (int)cnt[i] : 0;
    sm2[tid] = v;
    __syncthreads();
#pragma unroll
    for (int off = 1; off < 1024; off <<= 1) {
        int t2 = (tid >= off) ? sm2[tid - off] : 0;
        __syncthreads();
        sm2[tid] += t2;
        __syncthreads();
    }
    if (i < NN) excl[i] = sm2[tid] - v;
    if (tid == 1023) bsum[rel * 128 + blockIdx.x] = sm2[1023];
}
// launch #3: apply block offsets (bsum summed in-kernel; scan2 folded in) + seed cursor
__global__ void scan3m(const float* __restrict__ rs, int* __restrict__ indptr,
                       const int* __restrict__ bsum, int* __restrict__ cursor) {
    const int rel = blockIdx.y;
    const float* cnt = rs + (size_t)(2 * rel + 1) * NN;
    int* excl = indptr + rel * (NN + 1);
    int i = blockIdx.x * blockDim.x + threadIdx.x;
    if (i < NN) {
        int b = i >> 10;
        int off = 0;
        for (int j = 0; j < b; j++) off += bsum[rel * 128 + j];  // uniform per block, L1-hit
        int e = excl[i] + off;
        excl[i] = e;
        cursor[rel * NN + i] = e;
        if (i == NN - 1) excl[NN] = e + (int)cnt[i];
    }
}
// launch #4: fused fill(y=0..2) + [rsqrt | transpose | to_half](y=3)
#define MISC_RSQ_BLKS   2344    // ceil(600000/256)
#define MISC_TRW_BLKS   576     // 9*128*128/256
#define MISC_F16_BLKS   25000   // 2*NN*DIM/4/256
__global__ void misc_kernel(const int* __restrict__ s0, const int* __restrict__ d0, int n0,
                            const int* __restrict__ s1, const int* __restrict__ d1, int n1,
                            const int* __restrict__ s2, const int* __restrict__ d2, int n2,
                            int* __restrict__ cursor, int* __restrict__ eidx,
                            float* __restrict__ rs,
                            const float* __restrict__ Wa, const float* __restrict__ Wb,
                            const float* __restrict__ Wc, float* __restrict__ Wt,
                            const float* __restrict__ fd, const float* __restrict__ fp,
                            __half* __restrict__ od, __half* __restrict__ op) {
    const int y = blockIdx.y;
    if (y < 3) {   // CSR fill for relation y
        const int* src = y == 0 ? s0 : (y == 1 ? s1 : s2);
        const int* dst = y == 0 ? d0 : (y == 1 ? d1 : d2);
        int nE = y == 0 ? n0 : (y == 1 ? n1 : n2);
        int e = blockIdx.x * blockDim.x + threadIdx.x;
        if (e < nE) {
            int p = atomicAdd(&cursor[y * NN + dst[e]], 1);
            eidx[(size_t)y * NEMAX + p] = src[e];
        }
        return;
    }
    // y == 3: independent jobs, partitioned by blockIdx.x
    int bx = blockIdx.x;
    if (bx < MISC_RSQ_BLKS) {
        int i = bx * 256 + threadIdx.x;
        if (i < 6 * NN) rs[i] = rsqrtf(fmaxf(rs[i], 1.0f));
    } else if (bx < MISC_RSQ_BLKS + MISC_TRW_BLKS) {
        int i = (bx - MISC_RSQ_BLKS) * 256 + threadIdx.x;   // < 9*128*128
        int grp = i / (3 * DIM * DIM);
        int rem3 = i - grp * 3 * DIM * DIM;
        const float* W = grp == 0 ? Wa : (grp == 1 ? Wb : Wc);
        int rel = rem3 >> 14, rem = rem3 & 16383;
        int k = rem >> 7, n = rem & 127;
        float v = W[(rel << 14) + (k << 7) + n];
        uint32_t u;
        asm("cvt.rna.tf32.f32 %0, %1;" : "=r"(u) : "f"(v));
        Wt[i - rem + (n << 7) + k] = __uint_as_float(u);
    } else {
        const int n4 = NN * DIM / 4;
        int i = (bx - MISC_RSQ_BLKS - MISC_TRW_BLKS) * 256 + threadIdx.x;
        if (i < n4) {
            float4 v = __ldg(reinterpret_cast<const float4*>(fd) + i);
            reinterpret_cast<__half2*>(od)[2 * i]     = __floats2half2_rn(v.x, v.y);
            reinterpret_cast<__half2*>(od)[2 * i + 1] = __floats2half2_rn(v.z, v.w);
        } else if (i < 2 * n4) {
            int j = i - n4;
            float4 v = __ldg(reinterpret_cast<const float4*>(fp) + j);
            reinterpret_cast<__half2*>(op)[2 * j]     = __floats2half2_rn(v.x, v.y);
            reinterpret_cast<__half2*>(op)[2 * j + 1] = __floats2half2_rn(v.z, v.w);
        }
    }
}

// ---------------- launch #5 (ncu-profiled): batched CSR gather over fp16 features ----------------
__global__ void __launch_bounds__(256)
gather3(const __half* __restrict__ hd, const __half* __restrict__ hp,
        const int* __restrict__ indptr, const int* __restrict__ eidx,
        const float* __restrict__ rs,
        float* __restrict__ agg1, float* __restrict__ agg2, float* __restrict__ aggp) {
    const int rel = blockIdx.y;
    const __half* h = (rel == 0) ? hd : hp;
    const int*   ip  = indptr + rel * (NN + 1);
    const int*   ei  = eidx + (size_t)rel * NEMAX;
    const float* rso = rs + (size_t)(2 * rel) * NN;
    const float* rsi = rs + (size_t)(2 * rel + 1) * NN;
    float* agg = (rel == 0) ? agg1 : ((rel == 1) ? agg2 : aggp);

    int w = (blockIdx.x * blockDim.x + threadIdx.x) >> 5;
    int lane = threadIdx.x & 31;
    if (w >= NN) return;
    int s0 = __ldg(ip + w), s1 = __ldg(ip + w + 1);
    float4 acc = make_float4(0.f, 0.f, 0.f, 0.f);
    for (int base = s0; base < s1; base += 32) {
        int m = min(32, s1 - base);
        int se = (lane < m) ? __ldg(ei + base + lane) : 0;
#pragma unroll 8
        for (int i = 0; i < m; i++) {
            int s = __shfl_sync(0xFFFFFFFFu, se, i);
            float sc = __ldg(rso + s);
            uint2 raw = __ldg(reinterpret_cast<const uint2*>(h + (size_t)s * DIM) + lane);
            __half2 h0 = *reinterpret_cast<__half2*>(&raw.x);
            __half2 h1 = *reinterpret_cast<__half2*>(&raw.y);
            float2 f0 = __half22float2(h0);
            float2 f1 = __half22float2(h1);
            acc.x += sc * f0.x; acc.y += sc * f0.y;
            acc.z += sc * f1.x; acc.w += sc * f1.y;
        }
    }
    float ri = __ldg(rsi + w);
    acc.x *= ri; acc.y *= ri; acc.z *= ri; acc.w *= ri;
    uint4 u;   // round to tf32 so the GEMM cp.asyncs raw bytes
    asm("cvt.rna.tf32.f32 %0, %1;" : "=r"(u.x) : "f"(acc.x));
    asm("cvt.rna.tf32.f32 %0, %1;" : "=r"(u.y) : "f"(acc.y));
    asm("cvt.rna.tf32.f32 %0, %1;" : "=r"(u.z) : "f"(acc.z));
    asm("cvt.rna.tf32.f32 %0, %1;" : "=r"(u.w) : "f"(acc.w));
    reinterpret_cast<uint4*>(agg + (size_t)w * DIM)[lane] = u;
}

// ---------------- cp.async double-buffered tf32 GEMM ----------------
template<bool RELU, bool TWO, bool F16OUT>
__device__ __forceinline__ void gemm_body(
    int bx, const float* __restrict__ A1, const float* __restrict__ A2,
    const float* __restrict__ Wt1, const float* __restrict__ Wt2,
    const float* __restrict__ b1, const float* __restrict__ b2,
    void* __restrict__ out, int nrows, float* sm) {
    float* As = sm;                      // [2][128][SAK]
    float* Ws = sm + 2 * 128 * SAK;      // [2][128][SAK]

    const int t = threadIdx.x;
    const int lane = t & 31, wid = t >> 5;
    const int wm = wid >> 2, wn = wid & 3;
    const int row0 = bx * 128;
    const int qid = lane >> 2, qtl = lane & 3;

    float acc[4][4][4];
#pragma unroll
    for (int mi = 0; mi < 4; mi++)
#pragma unroll
        for (int ni = 0; ni < 4; ni++)
#pragma unroll
            for (int j = 0; j < 4; j++) acc[mi][ni][j] = 0.0f;

    const int C = TWO ? 8 : 4;

    auto issue = [&](int c) {
        int sidx = TWO ? (c >> 2) : 0;
        int kc   = TWO ? (c & 3) : c;
        const float* A = sidx ? A2 : A1;
        const float* W = sidx ? Wt2 : Wt1;
        int stage = c & 1;
        float* as = As + stage * 128 * SAK;
        float* ws = Ws + stage * 128 * SAK;
#pragma unroll
        for (int i = 0; i < 4; i++) {
            int idx = t + 256 * i;
            int r = idx >> 3, c4 = idx & 7;
            int row = row0 + r;
            int sz = (row < nrows) ? 16 : 0;
            cp_async16(sptr(as + r * SAK + c4 * 4), A + (size_t)row * DIM + kc * KC + c4 * 4, sz);
            cp_async16(sptr(ws + r * SAK + c4 * 4), W + (size_t)r * DIM + kc * KC + c4 * 4, 16);
        }
        asm volatile("cp.async.commit_group;" ::: "memory");
    };

    issue(0);
    issue(1);
    for (int c = 0; c < C; c++) {
        if (c == C - 1) asm volatile("cp.async.wait_group 0;" ::: "memory");
        else            asm volatile("cp.async.wait_group 1;" ::: "memory");
        __syncthreads();
        const int stage = c & 1;
        const float* as = As + stage * 128 * SAK;
        const float* ws = Ws + stage * 128 * SAK;
#pragma unroll
        for (int ks = 0; ks < 4; ks++) {
            const int k0 = ks * 8;
            uint32_t a[4][4], bf[4][2];
#pragma unroll
            for (int mi = 0; mi < 4; mi++) {
                const float* p = &as[(wm * 64 + mi * 16 + qid) * SAK + k0 + qtl];
                a[mi][0] = __float_as_uint(p[0]);
                a[mi][1] = __float_as_uint(p[8 * SAK]);
                a[mi][2] = __float_as_uint(p[4]);
                a[mi][3] = __float_as_uint(p[8 * SAK + 4]);
            }
#pragma unroll
            for (int ni = 0; ni < 4; ni++) {
                const float* p = &ws[(wn * 32 + ni * 8 + qid) * SAK + k0 + qtl];
                bf[ni][0] = __float_as_uint(p[0]);
                bf[ni][1] = __float_as_uint(p[4]);
            }
#pragma unroll
            for (int mi = 0; mi < 4; mi++)
#pragma unroll
                for (int ni = 0; ni < 4; ni++)
                    mma_tf32(acc[mi][ni], a[mi], bf[ni]);
        }
        __syncthreads();
        if (c + 2 < C) issue(c + 2);
    }

    // Epilogue
#pragma unroll
    for (int ni = 0; ni < 4; ni++) {
        int col = wn * 32 + ni * 8 + qtl * 2;
        float bb0 = __ldg(b1 + col)     + (TWO ? __ldg(b2 + col)     : 0.0f);
        float bb1 = __ldg(b1 + col + 1) + (TWO ? __ldg(b2 + col + 1) : 0.0f);
#pragma unroll
        for (int mi = 0; mi < 4; mi++) {
#pragma unroll
            for (int half = 0; half < 2; half++) {
                int r = row0 + wm * 64 + mi * 16 + qid + half * 8;
                if (r < nrows) {
                    float ox = acc[mi][ni][half * 2 + 0] + bb0;
                    float oy = acc[mi][ni][half * 2 + 1] + bb1;
                    if (RELU) { ox = fmaxf(ox, 0.0f); oy = fmaxf(oy, 0.0f); }
                    if (F16OUT) {
                        *reinterpret_cast<__half2*>(
                            (__half*)out + (size_t)r * DIM + col) = __floats2half2_rn(ox, oy);
                    } else {
                        float2 o; o.x = ox; o.y = oy;
                        *reinterpret_cast<float2*>((float*)out + (size_t)r * DIM + col) = o;
                    }
                }
            }
        }
    }
}

template<bool RELU, bool F16OUT>
__global__ void __launch_bounds__(256)
layer_mma(const float* __restrict__ agg1, const float* __restrict__ agg2,
          const float* __restrict__ aggp, const float* __restrict__ Wt,
          const float* __restrict__ bb, void* __restrict__ outd,
          void* __restrict__ outp, int split) {
    extern __shared__ float sm[];
    if ((int)blockIdx.x < split)
        gemm_body<RELU, true, F16OUT>(blockIdx.x, agg1, agg2,
                                      Wt, Wt + DIM * DIM, bb, bb + DIM, outd, NDRUG, sm);
    else
        gemm_body<RELU, false, F16OUT>(blockIdx.x - split, aggp, nullptr,
                                       Wt + 2 * DIM * DIM, nullptr, bb + 2 * DIM, nullptr,
                                       outp, NPROT, sm);
}

// ---------------- host orchestration ----------------
static const size_t GEMM_SMEM = 4u * 128u * SAK * sizeof(float);  // 73728 B

template<bool RELU, bool F16OUT>
static void launch_layer(const __half* hd_in, const __half* hp_in,
                         void* hd_out, void* hp_out,
                         const float* Wt, const float* b,
                         int* indptr, int* eidx,
                         float* agg1, float* agg2, float* aggp, float* rs) {
    gather3<<<dim3((NN * 32 + 255) / 256, 3), 256>>>(hd_in, hp_in, indptr, eidx, rs,
                                                     agg1, agg2, aggp);
    layer_mma<RELU, F16OUT><<<2 * GBLK, 256, GEMM_SMEM>>>(agg1, agg2, aggp, Wt, b,
                                                          hd_out, hp_out, GBLK);
}

extern "C" void kernel_launch(void* const* d_in, const int* in_sizes, int n_in,
                              void* d_out, int out_size) {
    const float* hd0   = (const float*)d_in[0];
    const float* hp0   = (const float*)d_in[1];
    const int*   ddi_s = (const int*)d_in[2];
    const int*   ddi_d = (const int*)d_in[3];
    const int*   pdi_s = (const int*)d_in[4];
    const int*   pdi_d = (const int*)d_in[5];
    const int*   ppi_s = (const int*)d_in[6];
    const int*   ppi_d = (const int*)d_in[7];
    const float* W1 = (const float*)d_in[8];
    const float* b1 = (const float*)d_in[9];
    const float* W2 = (const float*)d_in[10];
    const float* b2 = (const float*)d_in[11];
    const float* W3 = (const float*)d_in[12];
    const float* b3 = (const float*)d_in[13];

    const int nE_ddi = in_sizes[2];
    const int nE_pdi = in_sizes[4];
    const int nE_ppi = in_sizes[6];

    cudaFuncSetAttribute(layer_mma<true, true>,   cudaFuncAttributeMaxDynamicSharedMemorySize, (int)GEMM_SMEM);
    cudaFuncSetAttribute(layer_mma<false, false>, cudaFuncAttributeMaxDynamicSharedMemorySize, (int)GEMM_SMEM);

    float *agg1, *agg2, *aggp, *rs, *wt;
    __half *hA_d, *hA_p, *hB_d, *hB_p;
    int *indptr, *cursor, *eidx, *bsum;
    cudaGetSymbolAddress((void**)&hA_d, g_hA_d);
    cudaGetSymbolAddress((void**)&hA_p, g_hA_p);
    cudaGetSymbolAddress((void**)&hB_d, g_hB_d);
    cudaGetSymbolAddress((void**)&hB_p, g_hB_p);
    cudaGetSymbolAddress((void**)&agg1, g_agg1);
    cudaGetSymbolAddress((void**)&agg2, g_agg2);
    cudaGetSymbolAddress((void**)&aggp, g_aggp);
    cudaGetSymbolAddress((void**)&rs, g_rs);
    cudaGetSymbolAddress((void**)&wt, g_Wt);
    cudaGetSymbolAddress((void**)&indptr, g_indptr);
    cudaGetSymbolAddress((void**)&cursor, g_cursor);
    cudaGetSymbolAddress((void**)&eidx, g_eidx);
    cudaGetSymbolAddress((void**)&bsum, g_bsum);

    int nEmax = nE_ddi > nE_pdi ? nE_ddi : nE_pdi;
    if (nE_ppi > nEmax) nEmax = nE_ppi;

    // launches 0-4 (fixed count so ncu -s 5 profiles gather3)
    zero_rs<<<(6 * NN + 255) / 256, 256>>>(rs);
    count2b<<<dim3((nEmax + 255) / 256, 3), 256>>>(
        ddi_s, ddi_d, nE_ddi, pdi_s, pdi_d, nE_pdi, ppi_s, ppi_d, nE_ppi, rs);
    scan1<<<dim3((NN + 1023) / 1024, 3), 1024>>>(rs, indptr, bsum);
    scan3m<<<dim3((NN + 255) / 256, 3), 256>>>(rs, indptr, bsum, cursor);
    {
        int fill_x = (nEmax + 255) / 256;
        int misc_x = MISC_RSQ_BLKS + MISC_TRW_BLKS + MISC_F16_BLKS;
        int gx = fill_x > misc_x ? fill_x : misc_x;
        misc_kernel<<<dim3(gx, 4), 256>>>(
            ddi_s, ddi_d, nE_ddi, pdi_s, pdi_d, nE_pdi, ppi_s, ppi_d, nE_ppi,
            cursor, eidx, rs, W1, W2, W3, wt, hd0, hp0, hA_d, hA_p);
    }

    float* outd = (float*)d_out;
    float* outp = outd + (size_t)NDRUG * DIM;

    // layer 1: A(fp16 inputs) -> B(fp16), ReLU     [launches 5,6]
    launch_layer<true, true>(hA_d, hA_p, hB_d, hB_p,
                             wt + 0 * 3 * DIM * DIM, b1, indptr, eidx, agg1, agg2, aggp, rs);
    // layer 2: B -> A(fp16), ReLU                  [launches 7,8]
    launch_layer<true, true>(hB_d, hB_p, hA_d, hA_p,
                             wt + 1 * 3 * DIM * DIM, b2, indptr, eidx, agg1, agg2, aggp, rs);
    // layer 3: A -> d_out (fp32), no activation    [launches 9,10]
    launch_layer<false, false>(hA_d, hA_p, outd, outp,
                               wt + 2 * 3 * DIM * DIM, b3, indptr, eidx, agg1, agg2, aggp, rs);
}

// round 10
// speedup vs baseline: 1.0788x; 1.0788x over previous
#include <cuda_runtime.h>
#include <cuda_fp16.h>
#include <cstdint>

#define NDRUG 100000
#define NPROT 100000
#define NN    100000
#define NEMAX 800000
#define DIM   128
#define KC    32        // k-chunk
#define SAK   36        // smem chunk row stride (floats)
#define GBLK  782       // ceil(100000/128)

// ---------------- scratch ----------------
// fp16 feature buffers (ping-pong): A = inputs / layer2 out, B = layer1 out
__device__ __half g_hA_d[(size_t)NN * DIM];
__device__ __half g_hA_p[(size_t)NN * DIM];
__device__ __half g_hB_d[(size_t)NN * DIM];
__device__ __half g_hB_p[(size_t)NN * DIM];
__device__ float g_agg1[(size_t)NDRUG * DIM];
__device__ float g_agg2[(size_t)NDRUG * DIM];
__device__ float g_aggp[(size_t)NPROT * DIM];
// [0]=ddi_out [1]=ddi_in [2]=pdi_out [3]=pdi_in [4]=ppi_out [5]=ppi_in
__device__ float g_rs[(size_t)6 * NN];
__device__ float g_Wt[(size_t)9 * DIM * DIM];
__device__ int g_indptr[3 * (NN + 1)];
__device__ int g_cursor[3 * NN];
__device__ int g_eidx[3 * NEMAX];
__device__ int g_bsum[3 * 128];

// ---------------- helpers ----------------
__device__ __forceinline__ uint32_t sptr(const void* p) {
    return (uint32_t)__cvta_generic_to_shared(p);
}
__device__ __forceinline__ void cp_async16(uint32_t dst, const void* src, int sz) {
    asm volatile("cp.async.cg.shared.global [%0], [%1], 16, %2;" :: "r"(dst), "l"(src), "r"(sz));
}
__device__ __forceinline__ void mma_tf32(float c[4], const uint32_t a[4], const uint32_t b[2]) {
    asm volatile(
        "mma.sync.aligned.m16n8k8.row.col.f32.tf32.tf32.f32 "
        "{%0,%1,%2,%3}, {%4,%5,%6,%7}, {%8,%9}, {%0,%1,%2,%3};"
        : "+f"(c[0]), "+f"(c[1]), "+f"(c[2]), "+f"(c[3])
        : "r"(a[0]), "r"(a[1]), "r"(a[2]), "r"(a[3]), "r"(b[0]), "r"(b[1]));
}

// ---------------- preprocessing kernels ----------------
__global__ void count2b(const int* __restrict__ s0, const int* __restrict__ d0, int n0,
                        const int* __restrict__ s1, const int* __restrict__ d1, int n1,
                        const int* __restrict__ s2, const int* __restrict__ d2, int n2,
                        float* __restrict__ rs) {
    const int rel = blockIdx.y;
    const int* src = rel == 0 ? s0 : (rel == 1 ? s1 : s2);
    const int* dst = rel == 0 ? d0 : (rel == 1 ? d1 : d2);
    int n = rel == 0 ? n0 : (rel == 1 ? n1 : n2);
    float* cs = rs + (size_t)(2 * rel) * NN;
    float* cd = rs + (size_t)(2 * rel + 1) * NN;
    int i = blockIdx.x * blockDim.x + threadIdx.x;
    if (i < n) {
        atomicAdd(&cs[src[i]], 1.0f);
        atomicAdd(&cd[dst[i]], 1.0f);
    }
}
__global__ void rsqrt_kernel(float* __restrict__ p, int n) {
    int i = blockIdx.x * blockDim.x + threadIdx.x;
    if (i < n) p[i] = rsqrtf(fmaxf(p[i], 1.0f));
}
__global__ void transpose_w9(const float* __restrict__ Wa, const float* __restrict__ Wb,
                             const float* __restrict__ Wc, float* __restrict__ Wt) {
    int i = blockIdx.x * blockDim.x + threadIdx.x;
    if (i < 9 * DIM * DIM) {
        int grp = i / (3 * DIM * DIM);
        int rem3 = i - grp * 3 * DIM * DIM;
        const float* W = grp == 0 ? Wa : (grp == 1 ? Wb : Wc);
        int rel = rem3 >> 14, rem = rem3 & 16383;
        int k = rem >> 7, n = rem & 127;
        float v = W[(rel << 14) + (k << 7) + n];
        uint32_t u;
        asm("cvt.rna.tf32.f32 %0, %1;" : "=r"(u) : "f"(v));
        Wt[i - rem + (n << 7) + k] = __uint_as_float(u);
    }
}
// convert input fp32 features to fp16 (both node types, one launch)
__global__ void to_f16(const float* __restrict__ a, const float* __restrict__ b,
                       __half* __restrict__ oa, __half* __restrict__ ob) {
    const int n4 = NN * DIM / 4;
    int i = blockIdx.x * blockDim.x + threadIdx.x;
    if (i < n4) {
        float4 v = __ldg(reinterpret_cast<const float4*>(a) + i);
        reinterpret_cast<__half2*>(oa)[2 * i]     = __floats2half2_rn(v.x, v.y);
        reinterpret_cast<__half2*>(oa)[2 * i + 1] = __floats2half2_rn(v.z, v.w);
    } else if (i < 2 * n4) {
        int j = i - n4;
        float4 v = __ldg(reinterpret_cast<const float4*>(b) + j);
        reinterpret_cast<__half2*>(ob)[2 * j]     = __floats2half2_rn(v.x, v.y);
        reinterpret_cast<__half2*>(ob)[2 * j + 1] = __floats2half2_rn(v.z, v.w);
    }
}

// ---------------- scans (batched over 3 relations) ----------------
__global__ void scan1(const float* __restrict__ rs, int* __restrict__ indptr,
                      int* __restrict__ bsum) {
    __shared__ int sm2[1024];
    const int rel = blockIdx.y;
    const float* cnt = rs + (size_t)(2 * rel + 1) * NN;
    int* excl = indptr + rel * (NN + 1);
    int tid = threadIdx.x;
    int i = blockIdx.x * 1024 + tid;
    int v = (i < NN) ? (int)cnt[i] : 0;
    sm2[tid] = v;
    __syncthreads();
#pragma unroll
    for (int off = 1; off < 1024; off <<= 1) {
        int t2 = (tid >= off) ? sm2[tid - off] : 0;
        __syncthreads();
        sm2[tid] += t2;
        __syncthreads();
    }
    if (i < NN) excl[i] = sm2[tid] - v;
    if (tid == 1023) bsum[rel * 128 + blockIdx.x] = sm2[1023];
}
__global__ void scan2(int* __restrict__ bsum, int nb) {
    __shared__ int sm2[256];
    const int rel = blockIdx.x;
    int tid = threadIdx.x;
    sm2[tid] = (tid < nb) ? bsum[rel * 128 + tid] : 0;
    __syncthreads();
#pragma unroll
    for (int off = 1; off < 256; off <<= 1) {
        int t2 = (tid >= off) ? sm2[tid - off] : 0;
        __syncthreads();
        sm2[tid] += t2;
        __syncthreads();
    }
    if (tid < nb) bsum[rel * 128 + tid] = sm2[tid];
}
__global__ void scan3(const float* __restrict__ rs, int* __restrict__ indptr,
                      const int* __restrict__ bsum, int* __restrict__ cursor) {
    const int rel = blockIdx.y;
    const float* cnt = rs + (size_t)(2 * rel + 1) * NN;
    int* excl = indptr + rel * (NN + 1);
    int i = blockIdx.x * blockDim.x + threadIdx.x;
    if (i < NN) {
        int b = i >> 10;
        int off = b ? bsum[rel * 128 + b - 1] : 0;
        int e = excl[i] + off;
        excl[i] = e;
        cursor[rel * NN + i] = e;
        if (i == NN - 1) excl[NN] = e + (int)cnt[i];
    }
}
__global__ void fill3_kernel(const int* __restrict__ s0, const int* __restrict__ d0, int n0,
                             const int* __restrict__ s1, const int* __restrict__ d1, int n1,
                             const int* __restrict__ s2, const int* __restrict__ d2, int n2,
                             int* __restrict__ cursor, int* __restrict__ eidx) {
    const int rel = blockIdx.y;
    const int* src = rel == 0 ? s0 : (rel == 1 ? s1 : s2);
    const int* dst = rel == 0 ? d0 : (rel == 1 ? d1 : d2);
    int nE = rel == 0 ? n0 : (rel == 1 ? n1 : n2);
    int e = blockIdx.x * blockDim.x + threadIdx.x;
    if (e < nE) {
        int p = atomicAdd(&cursor[rel * NN + dst[e]], 1);
        eidx[(size_t)rel * NEMAX + p] = src[e];
    }
}

// ---------------- batched CSR gather over fp16 features (grid.y = relation) ----------------
__global__ void __launch_bounds__(256)
gather3(const __half* __restrict__ hd, const __half* __restrict__ hp,
        const int* __restrict__ indptr, const int* __restrict__ eidx,
        const float* __restrict__ rs,
        float* __restrict__ agg1, float* __restrict__ agg2, float* __restrict__ aggp) {
    const int rel = blockIdx.y;
    const __half* h = (rel == 0) ? hd : hp;
    const int*   ip  = indptr + rel * (NN + 1);
    const int*   ei  = eidx + (size_t)rel * NEMAX;
    const float* rso = rs + (size_t)(2 * rel) * NN;
    const float* rsi = rs + (size_t)(2 * rel + 1) * NN;
    float* agg = (rel == 0) ? agg1 : ((rel == 1) ? agg2 : aggp);

    int w = (blockIdx.x * blockDim.x + threadIdx.x) >> 5;
    int lane = threadIdx.x & 31;
    if (w >= NN) return;
    int s0 = __ldg(ip + w), s1 = __ldg(ip + w + 1);
    float4 acc = make_float4(0.f, 0.f, 0.f, 0.f);
    for (int base = s0; base < s1; base += 32) {
        int m = min(32, s1 - base);
        int se = (lane < m) ? __ldg(ei + base + lane) : 0;
#pragma unroll 4
        for (int i = 0; i < m; i++) {
            int s = __shfl_sync(0xFFFFFFFFu, se, i);
            float sc = __ldg(rso + s);
            uint2 raw = __ldg(reinterpret_cast<const uint2*>(h + (size_t)s * DIM) + lane);
            __half2 h0 = *reinterpret_cast<__half2*>(&raw.x);
            __half2 h1 = *reinterpret_cast<__half2*>(&raw.y);
            float2 f0 = __half22float2(h0);
            float2 f1 = __half22float2(h1);
            acc.x += sc * f0.x; acc.y += sc * f0.y;
            acc.z += sc * f1.x; acc.w += sc * f1.y;
        }
    }
    float ri = __ldg(rsi + w);
    acc.x *= ri; acc.y *= ri; acc.z *= ri; acc.w *= ri;
    uint4 u;   // round to tf32 so the GEMM cp.asyncs raw bytes
    asm("cvt.rna.tf32.f32 %0, %1;" : "=r"(u.x) : "f"(acc.x));
    asm("cvt.rna.tf32.f32 %0, %1;" : "=r"(u.y) : "f"(acc.y));
    asm("cvt.rna.tf32.f32 %0, %1;" : "=r"(u.z) : "f"(acc.z));
    asm("cvt.rna.tf32.f32 %0, %1;" : "=r"(u.w) : "f"(acc.w));
    reinterpret_cast<uint4*>(agg + (size_t)w * DIM)[lane] = u;
}

// ---------------- cp.async double-buffered tf32 GEMM ----------------
template<bool RELU, bool TWO, bool F16OUT>
__device__ __forceinline__ void gemm_body(
    int bx, const float* __restrict__ A1, const float* __restrict__ A2,
    const float* __restrict__ Wt1, const float* __restrict__ Wt2,
    const float* __restrict__ b1, const float* __restrict__ b2,
    void* __restrict__ out, int nrows, float* sm) {
    float* As = sm;                      // [2][128][SAK]
    float* Ws = sm + 2 * 128 * SAK;      // [2][128][SAK]

    const int t = threadIdx.x;
    const int lane = t & 31, wid = t >> 5;
    const int wm = wid >> 2, wn = wid & 3;
    const int row0 = bx * 128;
    const int qid = lane >> 2, qtl = lane & 3;

    float acc[4][4][4];
#pragma unroll
    for (int mi = 0; mi < 4; mi++)
#pragma unroll
        for (int ni = 0; ni < 4; ni++)
#pragma unroll
            for (int j = 0; j < 4; j++) acc[mi][ni][j] = 0.0f;

    const int C = TWO ? 8 : 4;

    auto issue = [&](int c) {
        int sidx = TWO ? (c >> 2) : 0;
        int kc   = TWO ? (c & 3) : c;
        const float* A = sidx ? A2 : A1;
        const float* W = sidx ? Wt2 : Wt1;
        int stage = c & 1;
        float* as = As + stage * 128 * SAK;
        float* ws = Ws + stage * 128 * SAK;
#pragma unroll
        for (int i = 0; i < 4; i++) {
            int idx = t + 256 * i;
            int r = idx >> 3, c4 = idx & 7;
            int row = row0 + r;
            int sz = (row < nrows) ? 16 : 0;
            cp_async16(sptr(as + r * SAK + c4 * 4), A + (size_t)row * DIM + kc * KC + c4 * 4, sz);
            cp_async16(sptr(ws + r * SAK + c4 * 4), W + (size_t)r * DIM + kc * KC + c4 * 4, 16);
        }
        asm volatile("cp.async.commit_group;" ::: "memory");
    };

    issue(0);
    issue(1);
    for (int c = 0; c < C; c++) {
        if (c == C - 1) asm volatile("cp.async.wait_group 0;" ::: "memory");
        else            asm volatile("cp.async.wait_group 1;" ::: "memory");
        __syncthreads();
        const int stage = c & 1;
        const float* as = As + stage * 128 * SAK;
        const float* ws = Ws + stage * 128 * SAK;
#pragma unroll
        for (int ks = 0; ks < 4; ks++) {
            const int k0 = ks * 8;
            uint32_t a[4][4], bf[4][2];
#pragma unroll
            for (int mi = 0; mi < 4; mi++) {
                const float* p = &as[(wm * 64 + mi * 16 + qid) * SAK + k0 + qtl];
                a[mi][0] = __float_as_uint(p[0]);
                a[mi][1] = __float_as_uint(p[8 * SAK]);
                a[mi][2] = __float_as_uint(p[4]);
                a[mi][3] = __float_as_uint(p[8 * SAK + 4]);
            }
#pragma unroll
            for (int ni = 0; ni < 4; ni++) {
                const float* p = &ws[(wn * 32 + ni * 8 + qid) * SAK + k0 + qtl];
                bf[ni][0] = __float_as_uint(p[0]);
                bf[ni][1] = __float_as_uint(p[4]);
            }
#pragma unroll
            for (int mi = 0; mi < 4; mi++)
#pragma unroll
                for (int ni = 0; ni < 4; ni++)
                    mma_tf32(acc[mi][ni], a[mi], bf[ni]);
        }
        __syncthreads();
        if (c + 2 < C) issue(c + 2);
    }

    // Epilogue
#pragma unroll
    for (int ni = 0; ni < 4; ni++) {
        int col = wn * 32 + ni * 8 + qtl * 2;
        float bb0 = __ldg(b1 + col)     + (TWO ? __ldg(b2 + col)     : 0.0f);
        float bb1 = __ldg(b1 + col + 1) + (TWO ? __ldg(b2 + col + 1) : 0.0f);
#pragma unroll
        for (int mi = 0; mi < 4; mi++) {
#pragma unroll
            for (int half = 0; half < 2; half++) {
                int r = row0 + wm * 64 + mi * 16 + qid + half * 8;
                if (r < nrows) {
                    float ox = acc[mi][ni][half * 2 + 0] + bb0;
                    float oy = acc[mi][ni][half * 2 + 1] + bb1;
                    if (RELU) { ox = fmaxf(ox, 0.0f); oy = fmaxf(oy, 0.0f); }
                    if (F16OUT) {
                        *reinterpret_cast<__half2*>(
                            (__half*)out + (size_t)r * DIM + col) = __floats2half2_rn(ox, oy);
                    } else {
                        float2 o; o.x = ox; o.y = oy;
                        *reinterpret_cast<float2*>((float*)out + (size_t)r * DIM + col) = o;
                    }
                }
            }
        }
    }
}

template<bool RELU, bool F16OUT>
__global__ void __launch_bounds__(256)
layer_mma(const float* __restrict__ agg1, const float* __restrict__ agg2,
          const float* __restrict__ aggp, const float* __restrict__ Wt,
          const float* __restrict__ bb, void* __restrict__ outd,
          void* __restrict__ outp, int split) {
    extern __shared__ float sm[];
    if ((int)blockIdx.x < split)
        gemm_body<RELU, true, F16OUT>(blockIdx.x, agg1, agg2,
                                      Wt, Wt + DIM * DIM, bb, bb + DIM, outd, NDRUG, sm);
    else
        gemm_body<RELU, false, F16OUT>(blockIdx.x - split, aggp, nullptr,
                                       Wt + 2 * DIM * DIM, nullptr, bb + 2 * DIM, nullptr,
                                       outp, NPROT, sm);
}

// ---------------- host orchestration ----------------
static const size_t GEMM_SMEM = 4u * 128u * SAK * sizeof(float);  // 73728 B

template<bool RELU, bool F16OUT>
static void launch_layer(const __half* hd_in, const __half* hp_in,
                         void* hd_out, void* hp_out,
                         const float* Wt, const float* b,
                         int* indptr, int* eidx,
                         float* agg1, float* agg2, float* aggp, float* rs) {
    gather3<<<dim3((NN * 32 + 255) / 256, 3), 256>>>(hd_in, hp_in, indptr, eidx, rs,
                                                     agg1, agg2, aggp);
    layer_mma<RELU, F16OUT><<<2 * GBLK, 256, GEMM_SMEM>>>(agg1, agg2, aggp, Wt, b,
                                                          hd_out, hp_out, GBLK);
}

extern "C" void kernel_launch(void* const* d_in, const int* in_sizes, int n_in,
                              void* d_out, int out_size) {
    const float* hd0   = (const float*)d_in[0];
    const float* hp0   = (const float*)d_in[1];
    const int*   ddi_s = (const int*)d_in[2];
    const int*   ddi_d = (const int*)d_in[3];
    const int*   pdi_s = (const int*)d_in[4];
    const int*   pdi_d = (const int*)d_in[5];
    const int*   ppi_s = (const int*)d_in[6];
    const int*   ppi_d = (const int*)d_in[7];
    const float* W1 = (const float*)d_in[8];
    const float* b1 = (const float*)d_in[9];
    const float* W2 = (const float*)d_in[10];
    const float* b2 = (const float*)d_in[11];
    const float* W3 = (const float*)d_in[12];
    const float* b3 = (const float*)d_in[13];

    const int nE_ddi = in_sizes[2];
    const int nE_pdi = in_sizes[4];
    const int nE_ppi = in_sizes[6];

    cudaFuncSetAttribute(layer_mma<true, true>,   cudaFuncAttributeMaxDynamicSharedMemorySize, (int)GEMM_SMEM);
    cudaFuncSetAttribute(layer_mma<false, false>, cudaFuncAttributeMaxDynamicSharedMemorySize, (int)GEMM_SMEM);

    float *agg1, *agg2, *aggp, *rs, *wt;
    __half *hA_d, *hA_p, *hB_d, *hB_p;
    int *indptr, *cursor, *eidx, *bsum;
    cudaGetSymbolAddress((void**)&hA_d, g_hA_d);
    cudaGetSymbolAddress((void**)&hA_p, g_hA_p);
    cudaGetSymbolAddress((void**)&hB_d, g_hB_d);
    cudaGetSymbolAddress((void**)&hB_p, g_hB_p);
    cudaGetSymbolAddress((void**)&agg1, g_agg1);
    cudaGetSymbolAddress((void**)&agg2, g_agg2);
    cudaGetSymbolAddress((void**)&aggp, g_aggp);
    cudaGetSymbolAddress((void**)&rs, g_rs);
    cudaGetSymbolAddress((void**)&wt, g_Wt);
    cudaGetSymbolAddress((void**)&indptr, g_indptr);
    cudaGetSymbolAddress((void**)&cursor, g_cursor);
    cudaGetSymbolAddress((void**)&eidx, g_eidx);
    cudaGetSymbolAddress((void**)&bsum, g_bsum);

    transpose_w9<<<(9 * DIM * DIM + 255) / 256, 256>>>(W1, W2, W3, wt);
    to_f16<<<(2 * NN * DIM / 4 + 255) / 256, 256>>>(hd0, hp0, hA_d, hA_p);

    cudaMemsetAsync(rs, 0, (size_t)6 * NN * sizeof(float), 0);
    int nEmax = nE_ddi > nE_pdi ? nE_ddi : nE_pdi;
    if (nE_ppi > nEmax) nEmax = nE_ppi;
    count2b<<<dim3((nEmax + 255) / 256, 3), 256>>>(
        ddi_s, ddi_d, nE_ddi, pdi_s, pdi_d, nE_pdi, ppi_s, ppi_d, nE_ppi, rs);

    const int nb = (NN + 1023) / 1024;
    const int tb = (NN + 255) / 256;
    scan1<<<dim3(nb, 3), 1024>>>(rs, indptr, bsum);
    scan2<<<3, 256>>>(bsum, nb);
    scan3<<<dim3(tb, 3), 256>>>(rs, indptr, bsum, cursor);

    fill3_kernel<<<dim3((nEmax + 255) / 256, 3), 256>>>(
        ddi_s, ddi_d, nE_ddi, pdi_s, pdi_d, nE_pdi, ppi_s, ppi_d, nE_ppi, cursor, eidx);

    rsqrt_kernel<<<(6 * NN + 255) / 256, 256>>>(rs, 6 * NN);

    float* outd = (float*)d_out;
    float* outp = outd + (size_t)NDRUG * DIM;

    // layer 1: A(fp16 inputs) -> B(fp16), ReLU
    launch_layer<true, true>(hA_d, hA_p, hB_d, hB_p,
                             wt + 0 * 3 * DIM * DIM, b1, indptr, eidx, agg1, agg2, aggp, rs);
    // layer 2: B -> A(fp16), ReLU
    launch_layer<true, true>(hB_d, hB_p, hA_d, hA_p,
                             wt + 1 * 3 * DIM * DIM, b2, indptr, eidx, agg1, agg2, aggp, rs);
    // layer 3: A -> d_out (fp32), no activation
    launch_layer<false, false>(hA_d, hA_p, outd, outp,
                               wt + 2 * 3 * DIM * DIM, b3, indptr, eidx, agg1, agg2, aggp, rs);
}

// round 11
// speedup vs baseline: 1.2136x; 1.1250x over previous
#include <cuda_runtime.h>
#include <cuda_fp16.h>
#include <cstdint>

#define NDRUG 100000
#define NPROT 100000
#define NN    100000
#define NEMAX 800000
#define DIM   128
#define KC    32        // k-chunk
#define SAKH  40        // smem chunk row stride (fp16 units, 80B: conflict-free)
#define GBLK  782       // ceil(100000/128)

// ---------------- scratch ----------------
// fp16 feature buffers (ping-pong): A = inputs / layer2 out, B = layer1 out
__device__ __half g_hA_d[(size_t)NN * DIM];
__device__ __half g_hA_p[(size_t)NN * DIM];
__device__ __half g_hB_d[(size_t)NN * DIM];
__device__ __half g_hB_p[(size_t)NN * DIM];
// fp16 aggregates (gather output / GEMM A operand)
__device__ __half g_agg1[(size_t)NDRUG * DIM];
__device__ __half g_agg2[(size_t)NDRUG * DIM];
__device__ __half g_aggp[(size_t)NPROT * DIM];
// [0]=ddi_out [1]=ddi_in [2]=pdi_out [3]=pdi_in [4]=ppi_out [5]=ppi_in
__device__ float g_rs[(size_t)6 * NN];
// transposed fp16 weights: 9 matrices of [n][k]
__device__ __half g_Wt[(size_t)9 * DIM * DIM];
__device__ int g_indptr[3 * (NN + 1)];
__device__ int g_cursor[3 * NN];
__device__ int g_eidx[3 * NEMAX];
__device__ int g_bsum[3 * 128];

// ---------------- helpers ----------------
__device__ __forceinline__ uint32_t sptr(const void* p) {
    return (uint32_t)__cvta_generic_to_shared(p);
}
__device__ __forceinline__ void cp_async16(uint32_t dst, const void* src, int sz) {
    asm volatile("cp.async.cg.shared.global [%0], [%1], 16, %2;" :: "r"(dst), "l"(src), "r"(sz));
}
// m16n8k16 fp16 MMA, fp32 accumulate
__device__ __forceinline__ void mma_f16(float c[4], const uint32_t a[4], const uint32_t b[2]) {
    asm volatile(
        "mma.sync.aligned.m16n8k16.row.col.f32.f16.f16.f32 "
        "{%0,%1,%2,%3}, {%4,%5,%6,%7}, {%8,%9}, {%0,%1,%2,%3};"
        : "+f"(c[0]), "+f"(c[1]), "+f"(c[2]), "+f"(c[3])
        : "r"(a[0]), "r"(a[1]), "r"(a[2]), "r"(a[3]), "r"(b[0]), "r"(b[1]));
}

// ---------------- preprocessing kernels ----------------
__global__ void count2b(const int* __restrict__ s0, const int* __restrict__ d0, int n0,
                        const int* __restrict__ s1, const int* __restrict__ d1, int n1,
                        const int* __restrict__ s2, const int* __restrict__ d2, int n2,
                        float* __restrict__ rs) {
    const int rel = blockIdx.y;
    const int* src = rel == 0 ? s0 : (rel == 1 ? s1 : s2);
    const int* dst = rel == 0 ? d0 : (rel == 1 ? d1 : d2);
    int n = rel == 0 ? n0 : (rel == 1 ? n1 : n2);
    float* cs = rs + (size_t)(2 * rel) * NN;
    float* cd = rs + (size_t)(2 * rel + 1) * NN;
    int i = blockIdx.x * blockDim.x + threadIdx.x;
    if (i < n) {
        atomicAdd(&cs[src[i]], 1.0f);
        atomicAdd(&cd[dst[i]], 1.0f);
    }
}
__global__ void rsqrt_kernel(float* __restrict__ p, int n) {
    int i = blockIdx.x * blockDim.x + threadIdx.x;
    if (i < n) p[i] = rsqrtf(fmaxf(p[i], 1.0f));
}
// transpose all 9 [128x128] weight matrices to fp16 [n][k]
__global__ void transpose_w9(const float* __restrict__ Wa, const float* __restrict__ Wb,
                             const float* __restrict__ Wc, __half* __restrict__ Wt) {
    int i = blockIdx.x * blockDim.x + threadIdx.x;
    if (i < 9 * DIM * DIM) {
        int grp = i / (3 * DIM * DIM);
        int rem3 = i - grp * 3 * DIM * DIM;
        const float* W = grp == 0 ? Wa : (grp == 1 ? Wb : Wc);
        int rel = rem3 >> 14, rem = rem3 & 16383;
        int k = rem >> 7, n = rem & 127;
        float v = W[(rel << 14) + (k << 7) + n];
        Wt[i - rem + (n << 7) + k] = __float2half_rn(v);
    }
}
// convert input fp32 features to fp16 (both node types, one launch)
__global__ void to_f16(const float* __restrict__ a, const float* __restrict__ b,
                       __half* __restrict__ oa, __half* __restrict__ ob) {
    const int n4 = NN * DIM / 4;
    int i = blockIdx.x * blockDim.x + threadIdx.x;
    if (i < n4) {
        float4 v = __ldg(reinterpret_cast<const float4*>(a) + i);
        reinterpret_cast<__half2*>(oa)[2 * i]     = __floats2half2_rn(v.x, v.y);
        reinterpret_cast<__half2*>(oa)[2 * i + 1] = __floats2half2_rn(v.z, v.w);
    } else if (i < 2 * n4) {
        int j = i - n4;
        float4 v = __ldg(reinterpret_cast<const float4*>(b) + j);
        reinterpret_cast<__half2*>(ob)[2 * j]     = __floats2half2_rn(v.x, v.y);
        reinterpret_cast<__half2*>(ob)[2 * j + 1] = __floats2half2_rn(v.z, v.w);
    }
}

// ---------------- scans (batched over 3 relations) ----------------
__global__ void scan1(const float* __restrict__ rs, int* __restrict__ indptr,
                      int* __restrict__ bsum) {
    __shared__ int sm2[1024];
    const int rel = blockIdx.y;
    const float* cnt = rs + (size_t)(2 * rel + 1) * NN;
    int* excl = indptr + rel * (NN + 1);
    int tid = threadIdx.x;
    int i = blockIdx.x * 1024 + tid;
    int v = (i < NN) ? (int)cnt[i] : 0;
    sm2[tid] = v;
    __syncthreads();
#pragma unroll
    for (int off = 1; off < 1024; off <<= 1) {
        int t2 = (tid >= off) ? sm2[tid - off] : 0;
        __syncthreads();
        sm2[tid] += t2;
        __syncthreads();
    }
    if (i < NN) excl[i] = sm2[tid] - v;
    if (tid == 1023) bsum[rel * 128 + blockIdx.x] = sm2[1023];
}
__global__ void scan2(int* __restrict__ bsum, int nb) {
    __shared__ int sm2[256];
    const int rel = blockIdx.x;
    int tid = threadIdx.x;
    sm2[tid] = (tid < nb) ? bsum[rel * 128 + tid] : 0;
    __syncthreads();
#pragma unroll
    for (int off = 1; off < 256; off <<= 1) {
        int t2 = (tid >= off) ? sm2[tid - off] : 0;
        __syncthreads();
        sm2[tid] += t2;
        __syncthreads();
    }
    if (tid < nb) bsum[rel * 128 + tid] = sm2[tid];
}
__global__ void scan3(const float* __restrict__ rs, int* __restrict__ indptr,
                      const int* __restrict__ bsum, int* __restrict__ cursor) {
    const int rel = blockIdx.y;
    const float* cnt = rs + (size_t)(2 * rel + 1) * NN;
    int* excl = indptr + rel * (NN + 1);
    int i = blockIdx.x * blockDim.x + threadIdx.x;
    if (i < NN) {
        int b = i >> 10;
        int off = b ? bsum[rel * 128 + b - 1] : 0;
        int e = excl[i] + off;
        excl[i] = e;
        cursor[rel * NN + i] = e;
        if (i == NN - 1) excl[NN] = e + (int)cnt[i];
    }
}
__global__ void fill3_kernel(const int* __restrict__ s0, const int* __restrict__ d0, int n0,
                             const int* __restrict__ s1, const int* __restrict__ d1, int n1,
                             const int* __restrict__ s2, const int* __restrict__ d2, int n2,
                             int* __restrict__ cursor, int* __restrict__ eidx) {
    const int rel = blockIdx.y;
    const int* src = rel == 0 ? s0 : (rel == 1 ? s1 : s2);
    const int* dst = rel == 0 ? d0 : (rel == 1 ? d1 : d2);
    int nE = rel == 0 ? n0 : (rel == 1 ? n1 : n2);
    int e = blockIdx.x * blockDim.x + threadIdx.x;
    if (e < nE) {
        int p = atomicAdd(&cursor[rel * NN + dst[e]], 1);
        eidx[(size_t)rel * NEMAX + p] = src[e];
    }
}

// ---------------- batched CSR gather over fp16 features -> fp16 agg ----------------
__global__ void __launch_bounds__(256)
gather3(const __half* __restrict__ hd, const __half* __restrict__ hp,
        const int* __restrict__ indptr, const int* __restrict__ eidx,
        const float* __restrict__ rs,
        __half* __restrict__ agg1, __half* __restrict__ agg2, __half* __restrict__ aggp) {
    const int rel = blockIdx.y;
    const __half* h = (rel == 0) ? hd : hp;
    const int*   ip  = indptr + rel * (NN + 1);
    const int*   ei  = eidx + (size_t)rel * NEMAX;
    const float* rso = rs + (size_t)(2 * rel) * NN;
    const float* rsi = rs + (size_t)(2 * rel + 1) * NN;
    __half* agg = (rel == 0) ? agg1 : ((rel == 1) ? agg2 : aggp);

    int w = (blockIdx.x * blockDim.x + threadIdx.x) >> 5;
    int lane = threadIdx.x & 31;
    if (w >= NN) return;
    int s0 = __ldg(ip + w), s1 = __ldg(ip + w + 1);
    float4 acc = make_float4(0.f, 0.f, 0.f, 0.f);
    for (int base = s0; base < s1; base += 32) {
        int m = min(32, s1 - base);
        int se = (lane < m) ? __ldg(ei + base + lane) : 0;
#pragma unroll 4
        for (int i = 0; i < m; i++) {
            int s = __shfl_sync(0xFFFFFFFFu, se, i);
            float sc = __ldg(rso + s);
            uint2 raw = __ldg(reinterpret_cast<const uint2*>(h + (size_t)s * DIM) + lane);
            __half2 h0 = *reinterpret_cast<__half2*>(&raw.x);
            __half2 h1 = *reinterpret_cast<__half2*>(&raw.y);
            float2 f0 = __half22float2(h0);
            float2 f1 = __half22float2(h1);
            acc.x += sc * f0.x; acc.y += sc * f0.y;
            acc.z += sc * f1.x; acc.w += sc * f1.y;
        }
    }
    float ri = __ldg(rsi + w);
    acc.x *= ri; acc.y *= ri; acc.z *= ri; acc.w *= ri;
    __half2 o01 = __floats2half2_rn(acc.x, acc.y);
    __half2 o23 = __floats2half2_rn(acc.z, acc.w);
    uint2 o;
    o.x = *reinterpret_cast<uint32_t*>(&o01);
    o.y = *reinterpret_cast<uint32_t*>(&o23);
    reinterpret_cast<uint2*>(agg + (size_t)w * DIM)[lane] = o;
}

// ---------------- cp.async double-buffered fp16 HMMA GEMM ----------------
template<bool RELU, bool TWO, bool F16OUT>
__device__ __forceinline__ void gemm_body(
    int bx, const __half* __restrict__ A1, const __half* __restrict__ A2,
    const __half* __restrict__ Wt1, const __half* __restrict__ Wt2,
    const float* __restrict__ b1, const float* __restrict__ b2,
    void* __restrict__ out, int nrows, __half* sm) {
    __half* As = sm;                       // [2][128][SAKH]
    __half* Ws = sm + 2 * 128 * SAKH;      // [2][128][SAKH]

    const int t = threadIdx.x;
    const int lane = t & 31, wid = t >> 5;
    const int wm = wid >> 2, wn = wid & 3;
    const int row0 = bx * 128;
    const int qid = lane >> 2, qtl = lane & 3;

    float acc[4][4][4];
#pragma unroll
    for (int mi = 0; mi < 4; mi++)
#pragma unroll
        for (int ni = 0; ni < 4; ni++)
#pragma unroll
            for (int j = 0; j < 4; j++) acc[mi][ni][j] = 0.0f;

    const int C = TWO ? 8 : 4;

    auto issue = [&](int c) {
        int sidx = TWO ? (c >> 2) : 0;
        int kc   = TWO ? (c & 3) : c;
        const __half* A = sidx ? A2 : A1;
        const __half* W = sidx ? Wt2 : Wt1;
        int stage = c & 1;
        __half* as = As + stage * 128 * SAKH;
        __half* ws = Ws + stage * 128 * SAKH;
#pragma unroll
        for (int i = 0; i < 2; i++) {
            int idx = t + 256 * i;          // 0..511
            int r = idx >> 2, c4 = idx & 3; // 4 x 16B per 32-fp16 row chunk
            int row = row0 + r;
            int sz = (row < nrows) ? 16 : 0;
            cp_async16(sptr(as + r * SAKH + c4 * 8), A + (size_t)row * DIM + kc * KC + c4 * 8, sz);
            cp_async16(sptr(ws + r * SAKH + c4 * 8), W + (size_t)r * DIM + kc * KC + c4 * 8, 16);
        }
        asm volatile("cp.async.commit_group;" ::: "memory");
    };

    issue(0);
    issue(1);
    for (int c = 0; c < C; c++) {
        if (c == C - 1) asm volatile("cp.async.wait_group 0;" ::: "memory");
        else            asm volatile("cp.async.wait_group 1;" ::: "memory");
        __syncthreads();
        const int stage = c & 1;
        const __half* as = As + stage * 128 * SAKH;
        const __half* ws = Ws + stage * 128 * SAKH;
#pragma unroll
        for (int ks = 0; ks < 2; ks++) {      // 2 x k16 per 32-k chunk
            const int k0 = ks * 16;
            uint32_t a[4][4], bf[4][2];
#pragma unroll
            for (int mi = 0; mi < 4; mi++) {
                const __half* p = &as[(wm * 64 + mi * 16 + qid) * SAKH + k0 + 2 * qtl];
                a[mi][0] = *reinterpret_cast<const uint32_t*>(p);
                a[mi][1] = *reinterpret_cast<const uint32_t*>(p + 8 * SAKH);
                a[mi][2] = *reinterpret_cast<const uint32_t*>(p + 8);
                a[mi][3] = *reinterpret_cast<const uint32_t*>(p + 8 * SAKH + 8);
            }
#pragma unroll
            for (int ni = 0; ni < 4; ni++) {
                const __half* p = &ws[(wn * 32 + ni * 8 + qid) * SAKH + k0 + 2 * qtl];
                bf[ni][0] = *reinterpret_cast<const uint32_t*>(p);
                bf[ni][1] = *reinterpret_cast<const uint32_t*>(p + 8);
            }
#pragma unroll
            for (int mi = 0; mi < 4; mi++)
#pragma unroll
                for (int ni = 0; ni < 4; ni++)
                    mma_f16(acc[mi][ni], a[mi], bf[ni]);
        }
        __syncthreads();
        if (c + 2 < C) issue(c + 2);
    }

    // Epilogue
#pragma unroll
    for (int ni = 0; ni < 4; ni++) {
        int col = wn * 32 + ni * 8 + qtl * 2;
        float bb0 = __ldg(b1 + col)     + (TWO ? __ldg(b2 + col)     : 0.0f);
        float bb1 = __ldg(b1 + col + 1) + (TWO ? __ldg(b2 + col + 1) : 0.0f);
#pragma unroll
        for (int mi = 0; mi < 4; mi++) {
#pragma unroll
            for (int half = 0; half < 2; half++) {
                int r = row0 + wm * 64 + mi * 16 + qid + half * 8;
                if (r < nrows) {
                    float ox = acc[mi][ni][half * 2 + 0] + bb0;
                    float oy = acc[mi][ni][half * 2 + 1] + bb1;
                    if (RELU) { ox = fmaxf(ox, 0.0f); oy = fmaxf(oy, 0.0f); }
                    if (F16OUT) {
                        *reinterpret_cast<__half2*>(
                            (__half*)out + (size_t)r * DIM + col) = __floats2half2_rn(ox, oy);
                    } else {
                        float2 o; o.x = ox; o.y = oy;
                        *reinterpret_cast<float2*>((float*)out + (size_t)r * DIM + col) = o;
                    }
                }
            }
        }
    }
}

template<bool RELU, bool F16OUT>
__global__ void __launch_bounds__(256)
layer_mma(const __half* __restrict__ agg1, const __half* __restrict__ agg2,
          const __half* __restrict__ aggp, const __half* __restrict__ Wt,
          const float* __restrict__ bb, void* __restrict__ outd,
          void* __restrict__ outp, int split) {
    extern __shared__ __half smh[];
    if ((int)blockIdx.x < split)
        gemm_body<RELU, true, F16OUT>(blockIdx.x, agg1, agg2,
                                      Wt, Wt + DIM * DIM, bb, bb + DIM, outd, NDRUG, smh);
    else
        gemm_body<RELU, false, F16OUT>(blockIdx.x - split, aggp, nullptr,
                                       Wt + 2 * DIM * DIM, nullptr, bb + 2 * DIM, nullptr,
                                       outp, NPROT, smh);
}

// ---------------- host orchestration ----------------
static const size_t GEMM_SMEM = 4u * 128u * SAKH * sizeof(__half);  // 40960 B

template<bool RELU, bool F16OUT>
static void launch_layer(const __half* hd_in, const __half* hp_in,
                         void* hd_out, void* hp_out,
                         const __half* Wt, const float* b,
                         int* indptr, int* eidx,
                         __half* agg1, __half* agg2, __half* aggp, float* rs) {
    gather3<<<dim3((NN * 32 + 255) / 256, 3), 256>>>(hd_in, hp_in, indptr, eidx, rs,
                                                     agg1, agg2, aggp);
    layer_mma<RELU, F16OUT><<<2 * GBLK, 256, GEMM_SMEM>>>(agg1, agg2, aggp, Wt, b,
                                                          hd_out, hp_out, GBLK);
}

extern "C" void kernel_launch(void* const* d_in, const int* in_sizes, int n_in,
                              void* d_out, int out_size) {
    const float* hd0   = (const float*)d_in[0];
    const float* hp0   = (const float*)d_in[1];
    const int*   ddi_s = (const int*)d_in[2];
    const int*   ddi_d = (const int*)d_in[3];
    const int*   pdi_s = (const int*)d_in[4];
    const int*   pdi_d = (const int*)d_in[5];
    const int*   ppi_s = (const int*)d_in[6];
    const int*   ppi_d = (const int*)d_in[7];
    const float* W1 = (const float*)d_in[8];
    const float* b1 = (const float*)d_in[9];
    const float* W2 = (const float*)d_in[10];
    const float* b2 = (const float*)d_in[11];
    const float* W3 = (const float*)d_in[12];
    const float* b3 = (const float*)d_in[13];

    const int nE_ddi = in_sizes[2];
    const int nE_pdi = in_sizes[4];
    const int nE_ppi = in_sizes[6];

    cudaFuncSetAttribute(layer_mma<true, true>,   cudaFuncAttributeMaxDynamicSharedMemorySize, (int)GEMM_SMEM);
    cudaFuncSetAttribute(layer_mma<false, false>, cudaFuncAttributeMaxDynamicSharedMemorySize, (int)GEMM_SMEM);

    float *rs;
    __half *agg1, *agg2, *aggp, *wt;
    __half *hA_d, *hA_p, *hB_d, *hB_p;
    int *indptr, *cursor, *eidx, *bsum;
    cudaGetSymbolAddress((void**)&hA_d, g_hA_d);
    cudaGetSymbolAddress((void**)&hA_p, g_hA_p);
    cudaGetSymbolAddress((void**)&hB_d, g_hB_d);
    cudaGetSymbolAddress((void**)&hB_p, g_hB_p);
    cudaGetSymbolAddress((void**)&agg1, g_agg1);
    cudaGetSymbolAddress((void**)&agg2, g_agg2);
    cudaGetSymbolAddress((void**)&aggp, g_aggp);
    cudaGetSymbolAddress((void**)&rs, g_rs);
    cudaGetSymbolAddress((void**)&wt, g_Wt);
    cudaGetSymbolAddress((void**)&indptr, g_indptr);
    cudaGetSymbolAddress((void**)&cursor, g_cursor);
    cudaGetSymbolAddress((void**)&eidx, g_eidx);
    cudaGetSymbolAddress((void**)&bsum, g_bsum);

    transpose_w9<<<(9 * DIM * DIM + 255) / 256, 256>>>(W1, W2, W3, wt);
    to_f16<<<(2 * NN * DIM / 4 + 255) / 256, 256>>>(hd0, hp0, hA_d, hA_p);

    cudaMemsetAsync(rs, 0, (size_t)6 * NN * sizeof(float), 0);
    int nEmax = nE_ddi > nE_pdi ? nE_ddi : nE_pdi;
    if (nE_ppi > nEmax) nEmax = nE_ppi;
    count2b<<<dim3((nEmax + 255) / 256, 3), 256>>>(
        ddi_s, ddi_d, nE_ddi, pdi_s, pdi_d, nE_pdi, ppi_s, ppi_d, nE_ppi, rs);

    const int nb = (NN + 1023) / 1024;
    const int tb = (NN + 255) / 256;
    scan1<<<dim3(nb, 3), 1024>>>(rs, indptr, bsum);
    scan2<<<3, 256>>>(bsum, nb);
    scan3<<<dim3(tb, 3), 256>>>(rs, indptr, bsum, cursor);

    fill3_kernel<<<dim3((nEmax + 255) / 256, 3), 256>>>(
        ddi_s, ddi_d, nE_ddi, pdi_s, pdi_d, nE_pdi, ppi_s, ppi_d, nE_ppi, cursor, eidx);

    rsqrt_kernel<<<(6 * NN + 255) / 256, 256>>>(rs, 6 * NN);

    float* outd = (float*)d_out;
    float* outp = outd + (size_t)NDRUG * DIM;

    // layer 1: A(fp16 inputs) -> B(fp16), ReLU
    launch_layer<true, true>(hA_d, hA_p, hB_d, hB_p,
                             wt + 0 * 3 * DIM * DIM, b1, indptr, eidx, agg1, agg2, aggp, rs);
    // layer 2: B -> A(fp16), ReLU
    launch_layer<true, true>(hB_d, hB_p, hA_d, hA_p,
                             wt + 1 * 3 * DIM * DIM, b2, indptr, eidx, agg1, agg2, aggp, rs);
    // layer 3: A -> d_out (fp32), no activation
    launch_layer<false, false>(hA_d, hA_p, outd, outp,
                               wt + 2 * 3 * DIM * DIM, b3, indptr, eidx, agg1, agg2, aggp, rs);
}

// round 12
// speedup vs baseline: 1.2215x; 1.0066x over previous
#include <cuda_runtime.h>
#include <cuda_fp16.h>
#include <cstdint>

#define NDRUG 100000
#define NPROT 100000
#define NN    100000
#define NEMAX 800000
#define DIM   128
#define KC    32        // k-chunk
#define SAKH  40        // smem chunk row stride (fp16 units, 80B: conflict-free)
#define GBLK  782       // ceil(100000/128)

// ---------------- scratch ----------------
__device__ __half g_hA_d[(size_t)NN * DIM];
__device__ __half g_hA_p[(size_t)NN * DIM];
__device__ __half g_hB_d[(size_t)NN * DIM];
__device__ __half g_hB_p[(size_t)NN * DIM];
__device__ __half g_agg1[(size_t)NDRUG * DIM];
__device__ __half g_agg2[(size_t)NDRUG * DIM];
__device__ __half g_aggp[(size_t)NPROT * DIM];
// [0]=ddi_out [1]=ddi_in [2]=pdi_out [3]=pdi_in [4]=ppi_out [5]=ppi_in
__device__ float g_rs[(size_t)6 * NN];
__device__ __half g_Wt[(size_t)9 * DIM * DIM];  // transposed fp16 weights [layer][rel][n][k]
__device__ int g_indptr[3 * (NN + 1)];
__device__ int g_cursor[3 * NN];
__device__ int g_eidx[3 * NEMAX];
__device__ int g_bsum[3 * 128];

// ---------------- helpers ----------------
__device__ __forceinline__ uint32_t sptr(const void* p) {
    return (uint32_t)__cvta_generic_to_shared(p);
}
__device__ __forceinline__ void cp_async16(uint32_t dst, const void* src, int sz) {
    asm volatile("cp.async.cg.shared.global [%0], [%1], 16, %2;" :: "r"(dst), "l"(src), "r"(sz));
}
__device__ __forceinline__ void mma_f16(float c[4], const uint32_t a[4], const uint32_t b[2]) {
    asm volatile(
        "mma.sync.aligned.m16n8k16.row.col.f32.f16.f16.f32 "
        "{%0,%1,%2,%3}, {%4,%5,%6,%7}, {%8,%9}, {%0,%1,%2,%3};"
        : "+f"(c[0]), "+f"(c[1]), "+f"(c[2]), "+f"(c[3])
        : "r"(a[0]), "r"(a[1]), "r"(a[2]), "r"(a[3]), "r"(b[0]), "r"(b[1]));
}

// ---------------- launch #0: fused prep (transpose W | to_f16 | zero rs) ----------------
// grid: (2344, 3). Each y-slice grid-strides over its own work. No empty blocks.
#define PREP_X 2344
__global__ void prep_kernel(const float* __restrict__ Wa, const float* __restrict__ Wb,
                            const float* __restrict__ Wc, __half* __restrict__ Wt,
                            const float* __restrict__ fd, const float* __restrict__ fp,
                            __half* __restrict__ od, __half* __restrict__ op,
                            float* __restrict__ rs) {
    const int y = blockIdx.y;
    if (y == 0) {          // transpose+convert 9 weight matrices: 147456 elems
        for (int i = blockIdx.x * 256 + threadIdx.x; i < 9 * DIM * DIM; i += PREP_X * 256) {
            int grp = i / (3 * DIM * DIM);
            int rem3 = i - grp * 3 * DIM * DIM;
            const float* W = grp == 0 ? Wa : (grp == 1 ? Wb : Wc);
            int rel = rem3 >> 14, rem = rem3 & 16383;
            int k = rem >> 7, n = rem & 127;
            Wt[i - rem + (n << 7) + k] = __float2half_rn(W[(rel << 14) + (k << 7) + n]);
        }
    } else if (y == 1) {   // fp32 -> fp16 inputs: 2*NN*DIM/4 = 6.4M float4
        const int n4 = NN * DIM / 4;
        for (int i = blockIdx.x * 256 + threadIdx.x; i < 2 * n4; i += PREP_X * 256) {
            if (i < n4) {
                float4 v = __ldg(reinterpret_cast<const float4*>(fd) + i);
                reinterpret_cast<__half2*>(od)[2 * i]     = __floats2half2_rn(v.x, v.y);
                reinterpret_cast<__half2*>(od)[2 * i + 1] = __floats2half2_rn(v.z, v.w);
            } else {
                int j = i - n4;
                float4 v = __ldg(reinterpret_cast<const float4*>(fp) + j);
                reinterpret_cast<__half2*>(op)[2 * j]     = __floats2half2_rn(v.x, v.y);
                reinterpret_cast<__half2*>(op)[2 * j + 1] = __floats2half2_rn(v.z, v.w);
            }
        }
    } else {               // zero rs: 600000 floats
        int i = blockIdx.x * 256 + threadIdx.x;
        if (i < 6 * NN) rs[i] = 0.0f;
    }
}

// ---------------- launch #1: batched degree count ----------------
__global__ void count2b(const int* __restrict__ s0, const int* __restrict__ d0, int n0,
                        const int* __restrict__ s1, const int* __restrict__ d1, int n1,
                        const int* __restrict__ s2, const int* __restrict__ d2, int n2,
                        float* __restrict__ rs) {
    const int rel = blockIdx.y;
    const int* src = rel == 0 ? s0 : (rel == 1 ? s1 : s2);
    const int* dst = rel == 0 ? d0 : (rel == 1 ? d1 : d2);
    int n = rel == 0 ? n0 : (rel == 1 ? n1 : n2);
    float* cs = rs + (size_t)(2 * rel) * NN;
    float* cd = rs + (size_t)(2 * rel + 1) * NN;
    int i = blockIdx.x * blockDim.x + threadIdx.x;
    if (i < n) {
        atomicAdd(&cs[src[i]], 1.0f);
        atomicAdd(&cd[dst[i]], 1.0f);
    }
}

// ---------------- launch #2: per-1024-block scan ----------------
__global__ void scan1(const float* __restrict__ rs, int* __restrict__ indptr,
                      int* __restrict__ bsum) {
    __shared__ int sm2[1024];
    const int rel = blockIdx.y;
    const float* cnt = rs + (size_t)(2 * rel + 1) * NN;
    int* excl = indptr + rel * (NN + 1);
    int tid = threadIdx.x;
    int i = blockIdx.x * 1024 + tid;
    int v = (i < NN) ? (int)cnt[i] : 0;
    sm2[tid] = v;
    __syncthreads();
#pragma unroll
    for (int off = 1; off < 1024; off <<= 1) {
        int t2 = (tid >= off) ? sm2[tid - off] : 0;
        __syncthreads();
        sm2[tid] += t2;
        __syncthreads();
    }
    if (i < NN) excl[i] = sm2[tid] - v;
    if (tid == 1023) bsum[rel * 128 + blockIdx.x] = sm2[1023];
}

// ---------------- launch #3: apply block offsets (scan2 folded in) + seed cursor ----------------
__global__ void scan3m(const float* __restrict__ rs, int* __restrict__ indptr,
                       const int* __restrict__ bsum, int* __restrict__ cursor) {
    const int rel = blockIdx.y;
    const float* cnt = rs + (size_t)(2 * rel + 1) * NN;
    int* excl = indptr + rel * (NN + 1);
    int i = blockIdx.x * blockDim.x + threadIdx.x;
    if (i < NN) {
        int b = i >> 10;
        int off = 0;
        for (int j = 0; j < b; j++) off += bsum[rel * 128 + j];  // L1-hot, uniform per block
        int e = excl[i] + off;
        excl[i] = e;
        cursor[rel * NN + i] = e;
        if (i == NN - 1) excl[NN] = e + (int)cnt[i];
    }
}

// ---------------- launch #4: CSR fill (y=0..2) + rsqrt (y=3) ----------------
__global__ void fillr_kernel(const int* __restrict__ s0, const int* __restrict__ d0, int n0,
                             const int* __restrict__ s1, const int* __restrict__ d1, int n1,
                             const int* __restrict__ s2, const int* __restrict__ d2, int n2,
                             int* __restrict__ cursor, int* __restrict__ eidx,
                             float* __restrict__ rs) {
    const int y = blockIdx.y;
    if (y < 3) {
        const int* src = y == 0 ? s0 : (y == 1 ? s1 : s2);
        const int* dst = y == 0 ? d0 : (y == 1 ? d1 : d2);
        int nE = y == 0 ? n0 : (y == 1 ? n1 : n2);
        int e = blockIdx.x * blockDim.x + threadIdx.x;
        if (e < nE) {
            int p = atomicAdd(&cursor[y * NN + dst[e]], 1);
            eidx[(size_t)y * NEMAX + p] = src[e];
        }
    } else {
        int i = blockIdx.x * blockDim.x + threadIdx.x;
        if (i < 6 * NN) rs[i] = rsqrtf(fmaxf(rs[i], 1.0f));
    }
}

// ---------------- launch #5 (ncu-profiled): batched CSR gather ----------------
__global__ void __launch_bounds__(256)
gather3(const __half* __restrict__ hd, const __half* __restrict__ hp,
        const int* __restrict__ indptr, const int* __restrict__ eidx,
        const float* __restrict__ rs,
        __half* __restrict__ agg1, __half* __restrict__ agg2, __half* __restrict__ aggp) {
    const int rel = blockIdx.y;
    const __half* h = (rel == 0) ? hd : hp;
    const int*   ip  = indptr + rel * (NN + 1);
    const int*   ei  = eidx + (size_t)rel * NEMAX;
    const float* rso = rs + (size_t)(2 * rel) * NN;
    const float* rsi = rs + (size_t)(2 * rel + 1) * NN;
    __half* agg = (rel == 0) ? agg1 : ((rel == 1) ? agg2 : aggp);

    int w = (blockIdx.x * blockDim.x + threadIdx.x) >> 5;
    int lane = threadIdx.x & 31;
    if (w >= NN) return;
    int s0 = __ldg(ip + w), s1 = __ldg(ip + w + 1);
    float4 acc = make_float4(0.f, 0.f, 0.f, 0.f);
    for (int base = s0; base < s1; base += 32) {
        int m = min(32, s1 - base);
        int se = (lane < m) ? __ldg(ei + base + lane) : 0;
#pragma unroll 4
        for (int i = 0; i < m; i++) {
            int s = __shfl_sync(0xFFFFFFFFu, se, i);
            float sc = __ldg(rso + s);
            uint2 raw = __ldg(reinterpret_cast<const uint2*>(h + (size_t)s * DIM) + lane);
            __half2 h0 = *reinterpret_cast<__half2*>(&raw.x);
            __half2 h1 = *reinterpret_cast<__half2*>(&raw.y);
            float2 f0 = __half22float2(h0);
            float2 f1 = __half22float2(h1);
            acc.x += sc * f0.x; acc.y += sc * f0.y;
            acc.z += sc * f1.x; acc.w += sc * f1.y;
        }
    }
    float ri = __ldg(rsi + w);
    acc.x *= ri; acc.y *= ri; acc.z *= ri; acc.w *= ri;
    __half2 o01 = __floats2half2_rn(acc.x, acc.y);
    __half2 o23 = __floats2half2_rn(acc.z, acc.w);
    uint2 o;
    o.x = *reinterpret_cast<uint32_t*>(&o01);
    o.y = *reinterpret_cast<uint32_t*>(&o23);
    reinterpret_cast<uint2*>(agg + (size_t)w * DIM)[lane] = o;
}

// ---------------- cp.async double-buffered fp16 HMMA GEMM ----------------
template<bool RELU, bool TWO, bool F16OUT>
__device__ __forceinline__ void gemm_body(
    int bx, const __half* __restrict__ A1, const __half* __restrict__ A2,
    const __half* __restrict__ Wt1, const __half* __restrict__ Wt2,
    const float* __restrict__ b1, const float* __restrict__ b2,
    void* __restrict__ out, int nrows, __half* sm) {
    __half* As = sm;                       // [2][128][SAKH]
    __half* Ws = sm + 2 * 128 * SAKH;      // [2][128][SAKH]

    const int t = threadIdx.x;
    const int lane = t & 31, wid = t >> 5;
    const int wm = wid >> 2, wn = wid & 3;
    const int row0 = bx * 128;
    const int qid = lane >> 2, qtl = lane & 3;

    float acc[4][4][4];
#pragma unroll
    for (int mi = 0; mi < 4; mi++)
#pragma unroll
        for (int ni = 0; ni < 4; ni++)
#pragma unroll
            for (int j = 0; j < 4; j++) acc[mi][ni][j] = 0.0f;

    const int C = TWO ? 8 : 4;

    auto issue = [&](int c) {
        int sidx = TWO ? (c >> 2) : 0;
        int kc   = TWO ? (c & 3) : c;
        const __half* A = sidx ? A2 : A1;
        const __half* W = sidx ? Wt2 : Wt1;
        int stage = c & 1;
        __half* as = As + stage * 128 * SAKH;
        __half* ws = Ws + stage * 128 * SAKH;
#pragma unroll
        for (int i = 0; i < 2; i++) {
            int idx = t + 256 * i;
            int r = idx >> 2, c4 = idx & 3;
            int row = row0 + r;
            int sz = (row < nrows) ? 16 : 0;
            cp_async16(sptr(as + r * SAKH + c4 * 8), A + (size_t)row * DIM + kc * KC + c4 * 8, sz);
            cp_async16(sptr(ws + r * SAKH + c4 * 8), W + (size_t)r * DIM + kc * KC + c4 * 8, 16);
        }
        asm volatile("cp.async.commit_group;" ::: "memory");
    };

    issue(0);
    issue(1);
    for (int c = 0; c < C; c++) {
        if (c == C - 1) asm volatile("cp.async.wait_group 0;" ::: "memory");
        else            asm volatile("cp.async.wait_group 1;" ::: "memory");
        __syncthreads();
        const int stage = c & 1;
        const __half* as = As + stage * 128 * SAKH;
        const __half* ws = Ws + stage * 128 * SAKH;
#pragma unroll
        for (int ks = 0; ks < 2; ks++) {
            const int k0 = ks * 16;
            uint32_t a[4][4], bf[4][2];
#pragma unroll
            for (int mi = 0; mi < 4; mi++) {
                const __half* p = &as[(wm * 64 + mi * 16 + qid) * SAKH + k0 + 2 * qtl];
                a[mi][0] = *reinterpret_cast<const uint32_t*>(p);
                a[mi][1] = *reinterpret_cast<const uint32_t*>(p + 8 * SAKH);
                a[mi][2] = *reinterpret_cast<const uint32_t*>(p + 8);
                a[mi][3] = *reinterpret_cast<const uint32_t*>(p + 8 * SAKH + 8);
            }
#pragma unroll
            for (int ni = 0; ni < 4; ni++) {
                const __half* p = &ws[(wn * 32 + ni * 8 + qid) * SAKH + k0 + 2 * qtl];
                bf[ni][0] = *reinterpret_cast<const uint32_t*>(p);
                bf[ni][1] = *reinterpret_cast<const uint32_t*>(p + 8);
            }
#pragma unroll
            for (int mi = 0; mi < 4; mi++)
#pragma unroll
                for (int ni = 0; ni < 4; ni++)
                    mma_f16(acc[mi][ni], a[mi], bf[ni]);
        }
        __syncthreads();
        if (c + 2 < C) issue(c + 2);
    }

    // Epilogue
#pragma unroll
    for (int ni = 0; ni < 4; ni++) {
        int col = wn * 32 + ni * 8 + qtl * 2;
        float bb0 = __ldg(b1 + col)     + (TWO ? __ldg(b2 + col)     : 0.0f);
        float bb1 = __ldg(b1 + col + 1) + (TWO ? __ldg(b2 + col + 1) : 0.0f);
#pragma unroll
        for (int mi = 0; mi < 4; mi++) {
#pragma unroll
            for (int half = 0; half < 2; half++) {
                int r = row0 + wm * 64 + mi * 16 + qid + half * 8;
                if (r < nrows) {
                    float ox = acc[mi][ni][half * 2 + 0] + bb0;
                    float oy = acc[mi][ni][half * 2 + 1] + bb1;
                    if (RELU) { ox = fmaxf(ox, 0.0f); oy = fmaxf(oy, 0.0f); }
                    if (F16OUT) {
                        *reinterpret_cast<__half2*>(
                            (__half*)out + (size_t)r * DIM + col) = __floats2half2_rn(ox, oy);
                    } else {
                        float2 o; o.x = ox; o.y = oy;
                        *reinterpret_cast<float2*>((float*)out + (size_t)r * DIM + col) = o;
                    }
                }
            }
        }
    }
}

template<bool RELU, bool F16OUT>
__global__ void __launch_bounds__(256)
layer_mma(const __half* __restrict__ agg1, const __half* __restrict__ agg2,
          const __half* __restrict__ aggp, const __half* __restrict__ Wt,
          const float* __restrict__ bb, void* __restrict__ outd,
          void* __restrict__ outp, int split) {
    extern __shared__ __half smh[];
    if ((int)blockIdx.x < split)
        gemm_body<RELU, true, F16OUT>(blockIdx.x, agg1, agg2,
                                      Wt, Wt + DIM * DIM, bb, bb + DIM, outd, NDRUG, smh);
    else
        gemm_body<RELU, false, F16OUT>(blockIdx.x - split, aggp, nullptr,
                                       Wt + 2 * DIM * DIM, nullptr, bb + 2 * DIM, nullptr,
                                       outp, NPROT, smh);
}

// ---------------- host orchestration ----------------
static const size_t GEMM_SMEM = 4u * 128u * SAKH * sizeof(__half);  // 40960 B

template<bool RELU, bool F16OUT>
static void launch_layer(const __half* hd_in, const __half* hp_in,
                         void* hd_out, void* hp_out,
                         const __half* Wt, const float* b,
                         int* indptr, int* eidx,
                         __half* agg1, __half* agg2, __half* aggp, float* rs) {
    gather3<<<dim3((NN * 32 + 255) / 256, 3), 256>>>(hd_in, hp_in, indptr, eidx, rs,
                                                     agg1, agg2, aggp);
    layer_mma<RELU, F16OUT><<<2 * GBLK, 256, GEMM_SMEM>>>(agg1, agg2, aggp, Wt, b,
                                                          hd_out, hp_out, GBLK);
}

extern "C" void kernel_launch(void* const* d_in, const int* in_sizes, int n_in,
                              void* d_out, int out_size) {
    const float* hd0   = (const float*)d_in[0];
    const float* hp0   = (const float*)d_in[1];
    const int*   ddi_s = (const int*)d_in[2];
    const int*   ddi_d = (const int*)d_in[3];
    const int*   pdi_s = (const int*)d_in[4];
    const int*   pdi_d = (const int*)d_in[5];
    const int*   ppi_s = (const int*)d_in[6];
    const int*   ppi_d = (const int*)d_in[7];
    const float* W1 = (const float*)d_in[8];
    const float* b1 = (const float*)d_in[9];
    const float* W2 = (const float*)d_in[10];
    const float* b2 = (const float*)d_in[11];
    const float* W3 = (const float*)d_in[12];
    const float* b3 = (const float*)d_in[13];

    const int nE_ddi = in_sizes[2];
    const int nE_pdi = in_sizes[4];
    const int nE_ppi = in_sizes[6];

    cudaFuncSetAttribute(layer_mma<true, true>,   cudaFuncAttributeMaxDynamicSharedMemorySize, (int)GEMM_SMEM);
    cudaFuncSetAttribute(layer_mma<false, false>, cudaFuncAttributeMaxDynamicSharedMemorySize, (int)GEMM_SMEM);

    float *rs;
    __half *agg1, *agg2, *aggp, *wt;
    __half *hA_d, *hA_p, *hB_d, *hB_p;
    int *indptr, *cursor, *eidx, *bsum;
    cudaGetSymbolAddress((void**)&hA_d, g_hA_d);
    cudaGetSymbolAddress((void**)&hA_p, g_hA_p);
    cudaGetSymbolAddress((void**)&hB_d, g_hB_d);
    cudaGetSymbolAddress((void**)&hB_p, g_hB_p);
    cudaGetSymbolAddress((void**)&agg1, g_agg1);
    cudaGetSymbolAddress((void**)&agg2, g_agg2);
    cudaGetSymbolAddress((void**)&aggp, g_aggp);
    cudaGetSymbolAddress((void**)&rs, g_rs);
    cudaGetSymbolAddress((void**)&wt, g_Wt);
    cudaGetSymbolAddress((void**)&indptr, g_indptr);
    cudaGetSymbolAddress((void**)&cursor, g_cursor);
    cudaGetSymbolAddress((void**)&eidx, g_eidx);
    cudaGetSymbolAddress((void**)&bsum, g_bsum);

    int nEmax = nE_ddi > nE_pdi ? nE_ddi : nE_pdi;
    if (nE_ppi > nEmax) nEmax = nE_ppi;

    // launches 0-4 (fixed count so ncu -s 5 lands on gather3)
    prep_kernel<<<dim3(PREP_X, 3), 256>>>(W1, W2, W3, wt, hd0, hp0, hA_d, hA_p, rs);
    count2b<<<dim3((nEmax + 255) / 256, 3), 256>>>(
        ddi_s, ddi_d, nE_ddi, pdi_s, pdi_d, nE_pdi, ppi_s, ppi_d, nE_ppi, rs);
    scan1<<<dim3((NN + 1023) / 1024, 3), 1024>>>(rs, indptr, bsum);
    scan3m<<<dim3((NN + 255) / 256, 3), 256>>>(rs, indptr, bsum, cursor);
    fillr_kernel<<<dim3((nEmax + 255) / 256, 4), 256>>>(
        ddi_s, ddi_d, nE_ddi, pdi_s, pdi_d, nE_pdi, ppi_s, ppi_d, nE_ppi, cursor, eidx, rs);

    float* outd = (float*)d_out;
    float* outp = outd + (size_t)NDRUG * DIM;

    // layer 1 [launches 5(gather3, profiled), 6]
    launch_layer<true, true>(hA_d, hA_p, hB_d, hB_p,
                             wt + 0 * 3 * DIM * DIM, b1, indptr, eidx, agg1, agg2, aggp, rs);
    // layer 2 [launches 7, 8]
    launch_layer<true, true>(hB_d, hB_p, hA_d, hA_p,
                             wt + 1 * 3 * DIM * DIM, b2, indptr, eidx, agg1, agg2, aggp, rs);
    // layer 3 -> fp32 d_out [launches 9, 10]
    launch_layer<false, false>(hA_d, hA_p, outd, outp,
                               wt + 2 * 3 * DIM * DIM, b3, indptr, eidx, agg1, agg2, aggp, rs);
}

// round 13
// speedup vs baseline: 1.2841x; 1.0512x over previous
#include <cuda_runtime.h>
#include <cuda_fp16.h>
#include <cstdint>

#define NDRUG 100000
#define NPROT 100000
#define NN    100000
#define NEMAX 800000
#define DIM   128
#define KC    32        // k-chunk
#define SAKH  40        // smem chunk row stride (fp16 units, 80B: conflict-free)
#define GBLK  782       // ceil(100000/128)

// ---------------- scratch ----------------
// pre-scaled fp16 feature buffers (ping-pong A/B):
//   *_d  : drug features scaled by rs_ddi_out
//   *_p1 : protein features scaled by rs_pdi_out
//   *_p2 : protein features scaled by rs_ppi_out
__device__ __half g_sA_d [(size_t)NN * DIM];
__device__ __half g_sA_p1[(size_t)NN * DIM];
__device__ __half g_sA_p2[(size_t)NN * DIM];
__device__ __half g_sB_d [(size_t)NN * DIM];
__device__ __half g_sB_p1[(size_t)NN * DIM];
__device__ __half g_sB_p2[(size_t)NN * DIM];
__device__ __half g_agg1[(size_t)NDRUG * DIM];
__device__ __half g_agg2[(size_t)NDRUG * DIM];
__device__ __half g_aggp[(size_t)NPROT * DIM];
// [0]=ddi_out [1]=ddi_in [2]=pdi_out [3]=pdi_in [4]=ppi_out [5]=ppi_in
__device__ float g_rs[(size_t)6 * NN];
__device__ __half g_Wt[(size_t)9 * DIM * DIM];  // transposed fp16 weights [layer][rel][n][k]
__device__ int g_indptr[3 * (NN + 1)];
__device__ int g_cursor[3 * NN];
__device__ int g_eidx[3 * NEMAX];
__device__ int g_bsum[3 * 128];

// ---------------- helpers ----------------
__device__ __forceinline__ uint32_t sptr(const void* p) {
    return (uint32_t)__cvta_generic_to_shared(p);
}
__device__ __forceinline__ void cp_async16(uint32_t dst, const void* src, int sz) {
    asm volatile("cp.async.cg.shared.global [%0], [%1], 16, %2;" :: "r"(dst), "l"(src), "r"(sz));
}
__device__ __forceinline__ void mma_f16(float c[4], const uint32_t a[4], const uint32_t b[2]) {
    asm volatile(
        "mma.sync.aligned.m16n8k16.row.col.f32.f16.f16.f32 "
        "{%0,%1,%2,%3}, {%4,%5,%6,%7}, {%8,%9}, {%0,%1,%2,%3};"
        : "+f"(c[0]), "+f"(c[1]), "+f"(c[2]), "+f"(c[3])
        : "r"(a[0]), "r"(a[1]), "r"(a[2]), "r"(a[3]), "r"(b[0]), "r"(b[1]));
}

// ---------------- prep: transpose W to fp16 [n][k] + zero rs ----------------
#define PREP_X 2344
__global__ void prep_kernel(const float* __restrict__ Wa, const float* __restrict__ Wb,
                            const float* __restrict__ Wc, __half* __restrict__ Wt,
                            float* __restrict__ rs) {
    const int y = blockIdx.y;
    if (y == 0) {          // transpose+convert 9 weight matrices
        for (int i = blockIdx.x * 256 + threadIdx.x; i < 9 * DIM * DIM; i += PREP_X * 256) {
            int grp = i / (3 * DIM * DIM);
            int rem3 = i - grp * 3 * DIM * DIM;
            const float* W = grp == 0 ? Wa : (grp == 1 ? Wb : Wc);
            int rel = rem3 >> 14, rem = rem3 & 16383;
            int k = rem >> 7, n = rem & 127;
            Wt[i - rem + (n << 7) + k] = __float2half_rn(W[(rel << 14) + (k << 7) + n]);
        }
    } else {               // zero rs
        int i = blockIdx.x * 256 + threadIdx.x;
        if (i < 6 * NN) rs[i] = 0.0f;
    }
}

// ---------------- batched degree count ----------------
__global__ void count2b(const int* __restrict__ s0, const int* __restrict__ d0, int n0,
                        const int* __restrict__ s1, const int* __restrict__ d1, int n1,
                        const int* __restrict__ s2, const int* __restrict__ d2, int n2,
                        float* __restrict__ rs) {
    const int rel = blockIdx.y;
    const int* src = rel == 0 ? s0 : (rel == 1 ? s1 : s2);
    const int* dst = rel == 0 ? d0 : (rel == 1 ? d1 : d2);
    int n = rel == 0 ? n0 : (rel == 1 ? n1 : n2);
    float* cs = rs + (size_t)(2 * rel) * NN;
    float* cd = rs + (size_t)(2 * rel + 1) * NN;
    int i = blockIdx.x * blockDim.x + threadIdx.x;
    if (i < n) {
        atomicAdd(&cs[src[i]], 1.0f);
        atomicAdd(&cd[dst[i]], 1.0f);
    }
}

// ---------------- scans ----------------
__global__ void scan1(const float* __restrict__ rs, int* __restrict__ indptr,
                      int* __restrict__ bsum) {
    __shared__ int sm2[1024];
    const int rel = blockIdx.y;
    const float* cnt = rs + (size_t)(2 * rel + 1) * NN;
    int* excl = indptr + rel * (NN + 1);
    int tid = threadIdx.x;
    int i = blockIdx.x * 1024 + tid;
    int v = (i < NN) ? (int)cnt[i] : 0;
    sm2[tid] = v;
    __syncthreads();
#pragma unroll
    for (int off = 1; off < 1024; off <<= 1) {
        int t2 = (tid >= off) ? sm2[tid - off] : 0;
        __syncthreads();
        sm2[tid] += t2;
        __syncthreads();
    }
    if (i < NN) excl[i] = sm2[tid] - v;
    if (tid == 1023) bsum[rel * 128 + blockIdx.x] = sm2[1023];
}
__global__ void scan3m(const float* __restrict__ rs, int* __restrict__ indptr,
                       const int* __restrict__ bsum, int* __restrict__ cursor) {
    const int rel = blockIdx.y;
    const float* cnt = rs + (size_t)(2 * rel + 1) * NN;
    int* excl = indptr + rel * (NN + 1);
    int i = blockIdx.x * blockDim.x + threadIdx.x;
    if (i < NN) {
        int b = i >> 10;
        int off = 0;
        for (int j = 0; j < b; j++) off += bsum[rel * 128 + j];
        int e = excl[i] + off;
        excl[i] = e;
        cursor[rel * NN + i] = e;
        if (i == NN - 1) excl[NN] = e + (int)cnt[i];
    }
}
// CSR fill (y=0..2) + rsqrt (y=3)
__global__ void fillr_kernel(const int* __restrict__ s0, const int* __restrict__ d0, int n0,
                             const int* __restrict__ s1, const int* __restrict__ d1, int n1,
                             const int* __restrict__ s2, const int* __restrict__ d2, int n2,
                             int* __restrict__ cursor, int* __restrict__ eidx,
                             float* __restrict__ rs) {
    const int y = blockIdx.y;
    if (y < 3) {
        const int* src = y == 0 ? s0 : (y == 1 ? s1 : s2);
        const int* dst = y == 0 ? d0 : (y == 1 ? d1 : d2);
        int nE = y == 0 ? n0 : (y == 1 ? n1 : n2);
        int e = blockIdx.x * blockDim.x + threadIdx.x;
        if (e < nE) {
            int p = atomicAdd(&cursor[y * NN + dst[e]], 1);
            eidx[(size_t)y * NEMAX + p] = src[e];
        }
    } else {
        int i = blockIdx.x * blockDim.x + threadIdx.x;
        if (i < 6 * NN) rs[i] = rsqrtf(fmaxf(rs[i], 1.0f));
    }
}

// ---------------- scale fp32 inputs into the 3 pre-scaled fp16 buffers ----------------
// y=0: drug*rs_ddi_out -> sd ; y=1: prot*rs_pdi_out -> sp1 ; y=2: prot*rs_ppi_out -> sp2
__global__ void scale_inputs(const float* __restrict__ fd, const float* __restrict__ fp,
                             const float* __restrict__ rs,
                             __half* __restrict__ sd, __half* __restrict__ sp1,
                             __half* __restrict__ sp2) {
    const int y = blockIdx.y;
    const float* f   = (y == 0) ? fd : fp;
    const float* rsv = rs + (size_t)(2 * y) * NN;   // ddi_out / pdi_out / ppi_out
    __half* o = (y == 0) ? sd : ((y == 1) ? sp1 : sp2);
    const int n4 = NN * DIM / 4;
    int i = blockIdx.x * blockDim.x + threadIdx.x;
    if (i < n4) {
        float sc = __ldg(rsv + (i >> 5));           // 32 float4 per row
        float4 v = __ldg(reinterpret_cast<const float4*>(f) + i);
        reinterpret_cast<__half2*>(o)[2 * i]     = __floats2half2_rn(v.x * sc, v.y * sc);
        reinterpret_cast<__half2*>(o)[2 * i + 1] = __floats2half2_rn(v.z * sc, v.w * sc);
    }
}

// ---------------- batched CSR gather: half-warp per dst row, pre-scaled features ----------------
__global__ void __launch_bounds__(256)
gather3(const __half* __restrict__ sd, const __half* __restrict__ sp1,
        const __half* __restrict__ sp2,
        const int* __restrict__ indptr, const int* __restrict__ eidx,
        const float* __restrict__ rs,
        __half* __restrict__ agg1, __half* __restrict__ agg2, __half* __restrict__ aggp) {
    const int rel = blockIdx.y;
    const __half* h = (rel == 0) ? sd : ((rel == 1) ? sp1 : sp2);
    const int*   ip  = indptr + rel * (NN + 1);
    const int*   ei  = eidx + (size_t)rel * NEMAX;
    const float* rsi = rs + (size_t)(2 * rel + 1) * NN;
    __half* agg = (rel == 0) ? agg1 : ((rel == 1) ? agg2 : aggp);

    int row  = (blockIdx.x * blockDim.x + threadIdx.x) >> 4;   // half-warp per row
    int lane = threadIdx.x & 15;                                // 16 lanes x 16B = 256B row
    if (row >= NN) return;
    int s0 = __ldg(ip + row), s1 = __ldg(ip + row + 1);
    float accf[8];
#pragma unroll
    for (int j = 0; j < 8; j++) accf[j] = 0.0f;

    for (int base = s0; base < s1; base += 16) {
        int m = min(16, s1 - base);
        int se = (lane < m) ? __ldg(ei + base + lane) : 0;
#pragma unroll 4
        for (int i = 0; i < m; i++) {
            int s = __shfl_sync(0xFFFFFFFFu, se, i, 16);   // segment-relative broadcast
            uint4 raw = __ldg(reinterpret_cast<const uint4*>(h + (size_t)s * DIM) + lane);
            const __half2* hh = reinterpret_cast<const __half2*>(&raw);
#pragma unroll
            for (int j = 0; j < 4; j++) {
                float2 f = __half22float2(hh[j]);
                accf[2 * j]     += f.x;
                accf[2 * j + 1] += f.y;
            }
        }
    }
    float ri = __ldg(rsi + row);
    uint4 o;
    __half2* oh = reinterpret_cast<__half2*>(&o);
#pragma unroll
    for (int j = 0; j < 4; j++)
        oh[j] = __floats2half2_rn(accf[2 * j] * ri, accf[2 * j + 1] * ri);
    reinterpret_cast<uint4*>(agg + (size_t)row * DIM)[lane] = o;
}

// ---------------- cp.async double-buffered fp16 HMMA GEMM ----------------
// F16OUT layers write PRE-SCALED fp16 feature copies:
//   drug (TWO=true): out1 = feat * rso1  (ddi_out)
//   prot (TWO=false): out1 = feat * rso1 (pdi_out), out2 = feat * rso2 (ppi_out)
// Final layer (F16OUT=false): fp32 unscaled to out1.
template<bool RELU, bool TWO, bool F16OUT>
__device__ __forceinline__ void gemm_body(
    int bx, const __half* __restrict__ A1, const __half* __restrict__ A2,
    const __half* __restrict__ Wt1, const __half* __restrict__ Wt2,
    const float* __restrict__ b1, const float* __restrict__ b2,
    void* __restrict__ out1, void* __restrict__ out2,
    const float* __restrict__ rso1, const float* __restrict__ rso2,
    int nrows, __half* sm) {
    __half* As = sm;                       // [2][128][SAKH]
    __half* Ws = sm + 2 * 128 * SAKH;      // [2][128][SAKH]

    const int t = threadIdx.x;
    const int lane = t & 31, wid = t >> 5;
    const int wm = wid >> 2, wn = wid & 3;
    const int row0 = bx * 128;
    const int qid = lane >> 2, qtl = lane & 3;

    float acc[4][4][4];
#pragma unroll
    for (int mi = 0; mi < 4; mi++)
#pragma unroll
        for (int ni = 0; ni < 4; ni++)
#pragma unroll
            for (int j = 0; j < 4; j++) acc[mi][ni][j] = 0.0f;

    const int C = TWO ? 8 : 4;

    auto issue = [&](int c) {
        int sidx = TWO ? (c >> 2) : 0;
        int kc   = TWO ? (c & 3) : c;
        const __half* A = sidx ? A2 : A1;
        const __half* W = sidx ? Wt2 : Wt1;
        int stage = c & 1;
        __half* as = As + stage * 128 * SAKH;
        __half* ws = Ws + stage * 128 * SAKH;
#pragma unroll
        for (int i = 0; i < 2; i++) {
            int idx = t + 256 * i;
            int r = idx >> 2, c4 = idx & 3;
            int row = row0 + r;
            int sz = (row < nrows) ? 16 : 0;
            cp_async16(sptr(as + r * SAKH + c4 * 8), A + (size_t)row * DIM + kc * KC + c4 * 8, sz);
            cp_async16(sptr(ws + r * SAKH + c4 * 8), W + (size_t)r * DIM + kc * KC + c4 * 8, 16);
        }
        asm volatile("cp.async.commit_group;" ::: "memory");
    };

    issue(0);
    issue(1);
    for (int c = 0; c < C; c++) {
        if (c == C - 1) asm volatile("cp.async.wait_group 0;" ::: "memory");
        else            asm volatile("cp.async.wait_group 1;" ::: "memory");
        __syncthreads();
        const int stage = c & 1;
        const __half* as = As + stage * 128 * SAKH;
        const __half* ws = Ws + stage * 128 * SAKH;
#pragma unroll
        for (int ks = 0; ks < 2; ks++) {
            const int k0 = ks * 16;
            uint32_t a[4][4], bf[4][2];
#pragma unroll
            for (int mi = 0; mi < 4; mi++) {
                const __half* p = &as[(wm * 64 + mi * 16 + qid) * SAKH + k0 + 2 * qtl];
                a[mi][0] = *reinterpret_cast<const uint32_t*>(p);
                a[mi][1] = *reinterpret_cast<const uint32_t*>(p + 8 * SAKH);
                a[mi][2] = *reinterpret_cast<const uint32_t*>(p + 8);
                a[mi][3] = *reinterpret_cast<const uint32_t*>(p + 8 * SAKH + 8);
            }
#pragma unroll
            for (int ni = 0; ni < 4; ni++) {
                const __half* p = &ws[(wn * 32 + ni * 8 + qid) * SAKH + k0 + 2 * qtl];
                bf[ni][0] = *reinterpret_cast<const uint32_t*>(p);
                bf[ni][1] = *reinterpret_cast<const uint32_t*>(p + 8);
            }
#pragma unroll
            for (int mi = 0; mi < 4; mi++)
#pragma unroll
                for (int ni = 0; ni < 4; ni++)
                    mma_f16(acc[mi][ni], a[mi], bf[ni]);
        }
        __syncthreads();
        if (c + 2 < C) issue(c + 2);
    }

    // Epilogue
#pragma unroll
    for (int ni = 0; ni < 4; ni++) {
        int col = wn * 32 + ni * 8 + qtl * 2;
        float bb0 = __ldg(b1 + col)     + (TWO ? __ldg(b2 + col)     : 0.0f);
        float bb1 = __ldg(b1 + col + 1) + (TWO ? __ldg(b2 + col + 1) : 0.0f);
#pragma unroll
        for (int mi = 0; mi < 4; mi++) {
#pragma unroll
            for (int half = 0; half < 2; half++) {
                int r = row0 + wm * 64 + mi * 16 + qid + half * 8;
                if (r < nrows) {
                    float ox = acc[mi][ni][half * 2 + 0] + bb0;
                    float oy = acc[mi][ni][half * 2 + 1] + bb1;
                    if (RELU) { ox = fmaxf(ox, 0.0f); oy = fmaxf(oy, 0.0f); }
                    if (F16OUT) {
                        float sA = __ldg(rso1 + r);
                        *reinterpret_cast<__half2*>(
                            (__half*)out1 + (size_t)r * DIM + col) =
                            __floats2half2_rn(ox * sA, oy * sA);
                        if (!TWO) {
                            float sB = __ldg(rso2 + r);
                            *reinterpret_cast<__half2*>(
                                (__half*)out2 + (size_t)r * DIM + col) =
                                __floats2half2_rn(ox * sB, oy * sB);
                        }
                    } else {
                        float2 o; o.x = ox; o.y = oy;
                        *reinterpret_cast<float2*>((float*)out1 + (size_t)r * DIM + col) = o;
                    }
                }
            }
        }
    }
}

template<bool RELU, bool F16OUT>
__global__ void __launch_bounds__(256)
layer_mma(const __half* __restrict__ agg1, const __half* __restrict__ agg2,
          const __half* __restrict__ aggp, const __half* __restrict__ Wt,
          const float* __restrict__ bb, const float* __restrict__ rs,
          void* __restrict__ outd, void* __restrict__ outp1, void* __restrict__ outp2,
          int split) {
    extern __shared__ __half smh[];
    if ((int)blockIdx.x < split)
        gemm_body<RELU, true, F16OUT>(blockIdx.x, agg1, agg2,
                                      Wt, Wt + DIM * DIM, bb, bb + DIM,
                                      outd, nullptr, rs + 0 * NN, nullptr, NDRUG, smh);
    else
        gemm_body<RELU, false, F16OUT>(blockIdx.x - split, aggp, nullptr,
                                       Wt + 2 * DIM * DIM, nullptr, bb + 2 * DIM, nullptr,
                                       outp1, outp2, rs + 2 * NN, rs + 4 * NN, NPROT, smh);
}

// ---------------- host orchestration ----------------
static const size_t GEMM_SMEM = 4u * 128u * SAKH * sizeof(__half);  // 40960 B

template<bool RELU, bool F16OUT>
static void launch_layer(const __half* sd, const __half* sp1, const __half* sp2,
                         void* od, void* op1, void* op2,
                         const __half* Wt, const float* b,
                         int* indptr, int* eidx,
                         __half* agg1, __half* agg2, __half* aggp, float* rs) {
    gather3<<<dim3((NN * 16 + 255) / 256, 3), 256>>>(sd, sp1, sp2, indptr, eidx, rs,
                                                     agg1, agg2, aggp);
    layer_mma<RELU, F16OUT><<<2 * GBLK, 256, GEMM_SMEM>>>(agg1, agg2, aggp, Wt, b, rs,
                                                          od, op1, op2, GBLK);
}

extern "C" void kernel_launch(void* const* d_in, const int* in_sizes, int n_in,
                              void* d_out, int out_size) {
    const float* hd0   = (const float*)d_in[0];
    const float* hp0   = (const float*)d_in[1];
    const int*   ddi_s = (const int*)d_in[2];
    const int*   ddi_d = (const int*)d_in[3];
    const int*   pdi_s = (const int*)d_in[4];
    const int*   pdi_d = (const int*)d_in[5];
    const int*   ppi_s = (const int*)d_in[6];
    const int*   ppi_d = (const int*)d_in[7];
    const float* W1 = (const float*)d_in[8];
    const float* b1 = (const float*)d_in[9];
    const float* W2 = (const float*)d_in[10];
    const float* b2 = (const float*)d_in[11];
    const float* W3 = (const float*)d_in[12];
    const float* b3 = (const float*)d_in[13];

    const int nE_ddi = in_sizes[2];
    const int nE_pdi = in_sizes[4];
    const int nE_ppi = in_sizes[6];

    cudaFuncSetAttribute(layer_mma<true, true>,   cudaFuncAttributeMaxDynamicSharedMemorySize, (int)GEMM_SMEM);
    cudaFuncSetAttribute(layer_mma<false, false>, cudaFuncAttributeMaxDynamicSharedMemorySize, (int)GEMM_SMEM);

    float *rs;
    __half *agg1, *agg2, *aggp, *wt;
    __half *sA_d, *sA_p1, *sA_p2, *sB_d, *sB_p1, *sB_p2;
    int *indptr, *cursor, *eidx, *bsum;
    cudaGetSymbolAddress((void**)&sA_d,  g_sA_d);
    cudaGetSymbolAddress((void**)&sA_p1, g_sA_p1);
    cudaGetSymbolAddress((void**)&sA_p2, g_sA_p2);
    cudaGetSymbolAddress((void**)&sB_d,  g_sB_d);
    cudaGetSymbolAddress((void**)&sB_p1, g_sB_p1);
    cudaGetSymbolAddress((void**)&sB_p2, g_sB_p2);
    cudaGetSymbolAddress((void**)&agg1, g_agg1);
    cudaGetSymbolAddress((void**)&agg2, g_agg2);
    cudaGetSymbolAddress((void**)&aggp, g_aggp);
    cudaGetSymbolAddress((void**)&rs, g_rs);
    cudaGetSymbolAddress((void**)&wt, g_Wt);
    cudaGetSymbolAddress((void**)&indptr, g_indptr);
    cudaGetSymbolAddress((void**)&cursor, g_cursor);
    cudaGetSymbolAddress((void**)&eidx, g_eidx);
    cudaGetSymbolAddress((void**)&bsum, g_bsum);

    int nEmax = nE_ddi > nE_pdi ? nE_ddi : nE_pdi;
    if (nE_ppi > nEmax) nEmax = nE_ppi;

    // preprocessing
    prep_kernel<<<dim3(PREP_X, 2), 256>>>(W1, W2, W3, wt, rs);
    count2b<<<dim3((nEmax + 255) / 256, 3), 256>>>(
        ddi_s, ddi_d, nE_ddi, pdi_s, pdi_d, nE_pdi, ppi_s, ppi_d, nE_ppi, rs);
    scan1<<<dim3((NN + 1023) / 1024, 3), 1024>>>(rs, indptr, bsum);
    scan3m<<<dim3((NN + 255) / 256, 3), 256>>>(rs, indptr, bsum, cursor);
    fillr_kernel<<<dim3((nEmax + 255) / 256, 4), 256>>>(
        ddi_s, ddi_d, nE_ddi, pdi_s, pdi_d, nE_pdi, ppi_s, ppi_d, nE_ppi, cursor, eidx, rs);
    scale_inputs<<<dim3((NN * DIM / 4 + 255) / 256, 3), 256>>>(
        hd0, hp0, rs, sA_d, sA_p1, sA_p2);

    float* outd = (float*)d_out;
    float* outp = outd + (size_t)NDRUG * DIM;

    // layer 1: A -> B (pre-scaled fp16), ReLU
    launch_layer<true, true>(sA_d, sA_p1, sA_p2, sB_d, sB_p1, sB_p2,
                             wt + 0 * 3 * DIM * DIM, b1, indptr, eidx, agg1, agg2, aggp, rs);
    // layer 2: B -> A, ReLU
    launch_layer<true, true>(sB_d, sB_p1, sB_p2, sA_d, sA_p1, sA_p2,
                             wt + 1 * 3 * DIM * DIM, b2, indptr, eidx, agg1, agg2, aggp, rs);
    // layer 3: A -> fp32 d_out, no activation
    launch_layer<false, false>(sA_d, sA_p1, sA_p2, outd, outp, nullptr,
                               wt + 2 * 3 * DIM * DIM, b3, indptr, eidx, agg1, agg2, aggp, rs);
}